// round 1
// baseline (speedup 1.0000x reference)
#include <cuda_runtime.h>
#include <cstdint>

#define SEQ 1024
#define BSZ 16
#define DIM 512
#define NH 8
#define NN (SEQ*BSZ)          // 16384 nodes
#define E0 (NN*32)            // 524288 edges
#define ETOT (E0+NN)          // + self loops

// ---------------- scratch (device globals; no cudaMalloc allowed) ----------
__device__ float g_h0[(size_t)NN*DIM];        // nodes @ W0 (pre-aggregation)
__device__ float g_h0act[(size_t)NN*DIM];     // layer0 output (elu)
__device__ float g_asrc0[NN*NH], g_adst0[NN*NH];
__device__ float g_asrc1[NN*NH], g_adst1[NN*NH];
__device__ float g_wsrc1[NH*DIM], g_wdst1[NH*DIM];
__device__ float g_agg1[(size_t)NN*NH*DIM];   // 268MB: per-head aggregated inputs
__device__ float g_wcat[(size_t)NH*DIM*DIM];  // permuted W1 * 1/8
__device__ int g_cnt[NN], g_fill[NN], g_rowptr[NN+1], g_col[ETOT];

// ---------------- helpers ----------------
__device__ __forceinline__ float lrelu(float v){ return v > 0.f ? v : 0.2f*v; }
__device__ __forceinline__ float eluf(float v){ return v > 0.f ? v : expm1f(v); }
__device__ __forceinline__ float warpMax(float v){
    #pragma unroll
    for(int o=16;o;o>>=1) v = fmaxf(v, __shfl_xor_sync(0xffffffffu, v, o));
    return v;
}
__device__ __forceinline__ float warpSum(float v){
    #pragma unroll
    for(int o=16;o;o>>=1) v += __shfl_xor_sync(0xffffffffu, v, o);
    return v;
}

// ---------------- CSR build ----------------
__global__ void k_zero(){
    int i = blockIdx.x*blockDim.x + threadIdx.x;
    if(i < NN){ g_cnt[i]=0; g_fill[i]=0; }
}
__global__ void k_count(const int* __restrict__ edge){
    int e = blockIdx.x*blockDim.x + threadIdx.x;
    if(e >= ETOT) return;
    int d = (e < E0) ? edge[E0+e] : (e-E0);
    atomicAdd(&g_cnt[d], 1);
}
__global__ void k_scan(){  // 1 block, 1024 threads; 16 nodes per thread
    __shared__ int sums[1024];
    int t = threadIdx.x;
    int base = t*16;
    int loc[16];
    int s = 0;
    #pragma unroll
    for(int i=0;i<16;i++){ loc[i] = s; s += g_cnt[base+i]; }
    sums[t] = s;
    __syncthreads();
    for(int off=1; off<1024; off<<=1){
        int v = 0;
        if(t >= off) v = sums[t-off];
        __syncthreads();
        if(t >= off) sums[t] += v;
        __syncthreads();
    }
    int pre = (t==0) ? 0 : sums[t-1];
    #pragma unroll
    for(int i=0;i<16;i++) g_rowptr[base+i] = pre + loc[i];
    if(t == 1023) g_rowptr[NN] = sums[1023];
}
__global__ void k_scatter(const int* __restrict__ edge){
    int e = blockIdx.x*blockDim.x + threadIdx.x;
    if(e >= ETOT) return;
    int s, d;
    if(e < E0){ s = edge[e]; d = edge[E0+e]; }
    else { s = e-E0; d = s; }
    int pos = g_rowptr[d] + atomicAdd(&g_fill[d], 1);
    g_col[pos] = s;
}

// ---------------- GEMM0: g_h0[N,512] = nodes @ W0 ----------------
// nodes row n = x[n%SEQ, n/SEQ, :]   (x is [SEQ,BSZ,DIM])
// tiles: 128x64, BK=16, 256 threads, 8x4 per thread
__global__ void k_gemm0(const float* __restrict__ x, const float* __restrict__ W0){
    __shared__ float As[16][128];
    __shared__ float Bs[16][64];
    int t = threadIdx.x;
    int tx = t & 15, ty = t >> 4;
    int row0 = blockIdx.y * 128;
    int col0 = blockIdx.x * 64;

    int m  = t >> 1;
    int kb = (t & 1) * 8;            // this thread covers kk kb..kb+7 of row m
    int gm = row0 + m;
    const float* arow = x + (size_t)((gm & (SEQ-1))*BSZ + (gm >> 10)) * DIM;
    int bkk = t >> 4, bn4 = t & 15;

    float acc[8][4];
    #pragma unroll
    for(int i=0;i<8;i++)
        #pragma unroll
        for(int j=0;j<4;j++) acc[i][j]=0.f;

    for(int k0=0; k0<DIM; k0+=16){
        float4 va = *(const float4*)(arow + k0 + kb);
        float4 vb = *(const float4*)(arow + k0 + kb + 4);
        As[kb+0][m]=va.x; As[kb+1][m]=va.y; As[kb+2][m]=va.z; As[kb+3][m]=va.w;
        As[kb+4][m]=vb.x; As[kb+5][m]=vb.y; As[kb+6][m]=vb.z; As[kb+7][m]=vb.w;
        *(float4*)&Bs[bkk][bn4*4] = *(const float4*)(W0 + (size_t)(k0+bkk)*DIM + col0 + bn4*4);
        __syncthreads();
        #pragma unroll
        for(int kk=0;kk<16;kk++){
            float4 b4 = *(float4*)&Bs[kk][tx*4];
            float4 a0 = *(float4*)&As[kk][ty*8];
            float4 a1 = *(float4*)&As[kk][ty*8+4];
            float ar[8] = {a0.x,a0.y,a0.z,a0.w,a1.x,a1.y,a1.z,a1.w};
            float br[4] = {b4.x,b4.y,b4.z,b4.w};
            #pragma unroll
            for(int i=0;i<8;i++)
                #pragma unroll
                for(int j=0;j<4;j++) acc[i][j] += ar[i]*br[j];
        }
        __syncthreads();
    }
    #pragma unroll
    for(int i=0;i<8;i++){
        int gm2 = row0 + ty*8 + i;
        float4 o = make_float4(acc[i][0],acc[i][1],acc[i][2],acc[i][3]);
        *(float4*)&g_h0[(size_t)gm2*DIM + col0 + tx*4] = o;
    }
}

// ---------------- alpha0: per-node per-head dot with att vectors ----------
__global__ void k_alpha0(const float* __restrict__ as0, const float* __restrict__ ad0){
    int n = blockIdx.x;
    int h = threadIdx.x >> 5, lane = threadIdx.x & 31;
    const float* hp = g_h0 + (size_t)n*DIM + h*64;
    float s=0.f, d=0.f;
    #pragma unroll
    for(int k=lane;k<64;k+=32){ float v=hp[k]; s += v*as0[h*64+k]; d += v*ad0[h*64+k]; }
    s = warpSum(s); d = warpSum(d);
    if(lane==0){ g_asrc0[n*NH+h]=s; g_adst0[n*NH+h]=d; }
}

// ---------------- aggregate0: softmax + weighted sum + bias + elu ---------
__global__ void k_agg0(const float* __restrict__ b0){
    int d = blockIdx.x;
    int h = threadIdx.x >> 5, lane = threadIdx.x & 31;
    int start = g_rowptr[d], deg = g_rowptr[d+1]-start;
    float adst = g_adst0[d*NH+h];
    float m = -1e30f;
    for(int i=lane;i<deg;i+=32){ int s=g_col[start+i]; m = fmaxf(m, lrelu(g_asrc0[s*NH+h]+adst)); }
    m = warpMax(m);
    float z = 0.f;
    for(int i=lane;i<deg;i+=32){ int s=g_col[start+i]; z += __expf(lrelu(g_asrc0[s*NH+h]+adst)-m); }
    z = warpSum(z);
    float invz = 1.f/(z + 1e-16f);
    float acc0=0.f, acc1=0.f;
    for(int i=0;i<deg;i++){
        int s = g_col[start+i];
        float w = __expf(lrelu(g_asrc0[s*NH+h]+adst)-m)*invz;
        const float* hp = g_h0 + (size_t)s*DIM + h*64;
        acc0 += w*hp[lane];
        acc1 += w*hp[lane+32];
    }
    int c = h*64 + lane;
    g_h0act[(size_t)d*DIM + c]      = eluf(acc0 + b0[c]);
    g_h0act[(size_t)d*DIM + c + 32] = eluf(acc1 + b0[c+32]);
}

// ---------------- weff1: wsrc[h,k] = sum_c W1[k, h*512+c]*att_src1[h,c] ---
__global__ void k_weff1(const float* __restrict__ W1, const float* __restrict__ as1,
                        const float* __restrict__ ad1){
    int w = blockIdx.x*8 + (threadIdx.x >> 5);
    int lane = threadIdx.x & 31;
    int h = w >> 9, k = w & 511;
    const float* wr = W1 + (size_t)k*(NH*DIM) + h*DIM;
    float s=0.f, d=0.f;
    for(int c=lane;c<DIM;c+=32){ float v=wr[c]; s += v*as1[h*DIM+c]; d += v*ad1[h*DIM+c]; }
    s = warpSum(s); d = warpSum(d);
    if(lane==0){ g_wsrc1[h*DIM+k]=s; g_wdst1[h*DIM+k]=d; }
}

// ---------------- alpha1 -------------------------------------------------
__global__ void k_alpha1(){
    int n = blockIdx.x;
    int h = threadIdx.x >> 5, lane = threadIdx.x & 31;
    const float* hp = g_h0act + (size_t)n*DIM;
    float s=0.f, d=0.f;
    for(int k=lane;k<DIM;k+=32){ float v=hp[k]; s += v*g_wsrc1[h*DIM+k]; d += v*g_wdst1[h*DIM+k]; }
    s = warpSum(s); d = warpSum(d);
    if(lane==0){ g_asrc1[n*NH+h]=s; g_adst1[n*NH+h]=d; }
}

// ---------------- aggregate1: agg[d, h*512+k] = sum_e w[e,h]*h0act[src,k] -
__global__ void k_agg1(){
    __shared__ float v[512];
    __shared__ float ws[8];
    __shared__ float sm[8];
    __shared__ float sinvz[8];
    int d = blockIdx.x;
    int t = threadIdx.x;
    int warp = t >> 5, lane = t & 31;
    int start = g_rowptr[d], deg = g_rowptr[d+1]-start;
    {
        int h = warp;
        float adst = g_adst1[d*NH+h];
        float m = -1e30f;
        for(int i=lane;i<deg;i+=32){ int s=g_col[start+i]; m = fmaxf(m, lrelu(g_asrc1[s*NH+h]+adst)); }
        m = warpMax(m);
        float z = 0.f;
        for(int i=lane;i<deg;i+=32){ int s=g_col[start+i]; z += __expf(lrelu(g_asrc1[s*NH+h]+adst)-m); }
        z = warpSum(z);
        if(lane==0){ sm[h]=m; sinvz[h]=1.f/(z+1e-16f); }
    }
    __syncthreads();
    float acc[8][2];
    #pragma unroll
    for(int h=0;h<8;h++){ acc[h][0]=0.f; acc[h][1]=0.f; }
    float adst_l = (t < 8) ? g_adst1[d*NH+t] : 0.f;
    for(int i=0;i<deg;i++){
        int s = g_col[start+i];
        v[t]     = g_h0act[(size_t)s*DIM + t];
        v[t+256] = g_h0act[(size_t)s*DIM + t + 256];
        if(t < 8) ws[t] = __expf(lrelu(g_asrc1[s*NH+t]+adst_l)-sm[t])*sinvz[t];
        __syncthreads();
        float a0 = v[t], a1 = v[t+256];
        float w[8];
        #pragma unroll
        for(int h=0;h<8;h++) w[h] = ws[h];
        #pragma unroll
        for(int h=0;h<8;h++){ acc[h][0] += w[h]*a0; acc[h][1] += w[h]*a1; }
        __syncthreads();
    }
    float* out = g_agg1 + (size_t)d*(NH*DIM);
    #pragma unroll
    for(int h=0;h<8;h++){
        out[h*DIM + t]       = acc[h][0];
        out[h*DIM + t + 256] = acc[h][1];
    }
}

// ---------------- wcat: Wcat[h*512+k, c] = W1[k, h*512+c]/8 --------------
__global__ void k_wcat(const float* __restrict__ W1){
    int i = blockIdx.x*blockDim.x + threadIdx.x;   // < 4096*512
    int c  = i & 511;
    int kk = i >> 9;          // h*512 + k
    int h = kk >> 9, k = kk & 511;
    g_wcat[i] = W1[(size_t)k*(NH*DIM) + h*DIM + c] * 0.125f;
}

// ---------------- GEMM final: out = elu(agg1 @ Wcat + b1) ----------------
__global__ void k_gemm1(const float* __restrict__ b1, float* __restrict__ out){
    __shared__ float As[16][128];
    __shared__ float Bs[16][64];
    int t = threadIdx.x;
    int tx = t & 15, ty = t >> 4;
    int row0 = blockIdx.y * 128;
    int col0 = blockIdx.x * 64;

    int m  = t >> 1;
    int kb = (t & 1) * 8;
    int gm = row0 + m;
    const float* arow = g_agg1 + (size_t)gm*(NH*DIM);
    int bkk = t >> 4, bn4 = t & 15;

    float acc[8][4];
    #pragma unroll
    for(int i=0;i<8;i++)
        #pragma unroll
        for(int j=0;j<4;j++) acc[i][j]=0.f;

    for(int k0=0; k0<NH*DIM; k0+=16){
        float4 va = *(const float4*)(arow + k0 + kb);
        float4 vb = *(const float4*)(arow + k0 + kb + 4);
        As[kb+0][m]=va.x; As[kb+1][m]=va.y; As[kb+2][m]=va.z; As[kb+3][m]=va.w;
        As[kb+4][m]=vb.x; As[kb+5][m]=vb.y; As[kb+6][m]=vb.z; As[kb+7][m]=vb.w;
        *(float4*)&Bs[bkk][bn4*4] = *(const float4*)(g_wcat + (size_t)(k0+bkk)*DIM + col0 + bn4*4);
        __syncthreads();
        #pragma unroll
        for(int kk=0;kk<16;kk++){
            float4 b4 = *(float4*)&Bs[kk][tx*4];
            float4 a0 = *(float4*)&As[kk][ty*8];
            float4 a1 = *(float4*)&As[kk][ty*8+4];
            float ar[8] = {a0.x,a0.y,a0.z,a0.w,a1.x,a1.y,a1.z,a1.w};
            float br[4] = {b4.x,b4.y,b4.z,b4.w};
            #pragma unroll
            for(int i=0;i<8;i++)
                #pragma unroll
                for(int j=0;j<4;j++) acc[i][j] += ar[i]*br[j];
        }
        __syncthreads();
    }
    int c = col0 + tx*4;
    float4 bb = *(const float4*)(b1 + c);
    #pragma unroll
    for(int i=0;i<8;i++){
        int gm2 = row0 + ty*8 + i;
        float4 o;
        o.x = eluf(acc[i][0] + bb.x);
        o.y = eluf(acc[i][1] + bb.y);
        o.z = eluf(acc[i][2] + bb.z);
        o.w = eluf(acc[i][3] + bb.w);
        *(float4*)&out[(size_t)gm2*DIM + c] = o;   // output reshape = raw reinterpret
    }
}

// ---------------- launch ----------------
extern "C" void kernel_launch(void* const* d_in, const int* in_sizes, int n_in,
                              void* d_out, int out_size){
    const float* x   = (const float*)d_in[0];
    const int*   edge= (const int*)  d_in[1];
    const float* W0  = (const float*)d_in[2];
    const float* as0 = (const float*)d_in[3];
    const float* ad0 = (const float*)d_in[4];
    const float* b0  = (const float*)d_in[5];
    const float* W1  = (const float*)d_in[6];
    const float* as1 = (const float*)d_in[7];
    const float* ad1 = (const float*)d_in[8];
    const float* b1  = (const float*)d_in[9];
    float* out = (float*)d_out;

    k_zero<<<(NN+255)/256, 256>>>();
    k_count<<<(ETOT+255)/256, 256>>>(edge);
    k_scan<<<1, 1024>>>();
    k_scatter<<<(ETOT+255)/256, 256>>>(edge);

    k_gemm0<<<dim3(DIM/64, NN/128), 256>>>(x, W0);
    k_alpha0<<<NN, 256>>>(as0, ad0);
    k_agg0<<<NN, 256>>>(b0);

    k_weff1<<<512, 256>>>(W1, as1, ad1);
    k_alpha1<<<NN, 256>>>();
    k_agg1<<<NN, 256>>>();
    k_wcat<<<(NH*DIM*DIM)/1024, 1024>>>(W1);
    k_gemm1<<<dim3(DIM/64, NN/128), 256>>>(b1, out);
}

// round 12
// speedup vs baseline: 1.0011x; 1.0011x over previous

#include <cuda_runtime.h>
#include <cstdint>

#define SEQ 1024
#define BSZ 16
#define DIM 512
#define NH 8
#define NN (SEQ*BSZ)          // 16384 nodes
#define E0 (NN*32)            // 524288 edges
#define ETOT (E0+NN)          // + self loops

// ---------------- scratch (device globals; no cudaMalloc allowed) ----------
__device__ float g_h0[(size_t)NN*DIM];        // nodes @ W0 (pre-aggregation)
__device__ float g_h0act[(size_t)NN*DIM];     // layer0 output (elu)
__device__ float g_asrc0[NN*NH], g_adst0[NN*NH];
__device__ float g_asrc1[NN*NH], g_adst1[NN*NH];
__device__ float g_wsrc1[NH*DIM], g_wdst1[NH*DIM];
__device__ float g_agg1[(size_t)NN*NH*DIM];   // 268MB: per-head aggregated inputs
__device__ float g_wcat[(size_t)NH*DIM*DIM];  // permuted W1 * 1/8
__device__ int g_cnt[NN], g_fill[NN], g_rowptr[NN+1], g_col[ETOT];

// ---------------- helpers ----------------
__device__ __forceinline__ float lrelu(float v){ return v > 0.f ? v : 0.2f*v; }
__device__ __forceinline__ float eluf(float v){ return v > 0.f ? v : expm1f(v); }
__device__ __forceinline__ float warpMax(float v){
    #pragma unroll
    for(int o=16;o;o>>=1) v = fmaxf(v, __shfl_xor_sync(0xffffffffu, v, o));
    return v;
}
__device__ __forceinline__ float warpSum(float v){
    #pragma unroll
    for(int o=16;o;o>>=1) v += __shfl_xor_sync(0xffffffffu, v, o);
    return v;
}

// ---------------- CSR build ----------------
__global__ void k_zero(){
    int i = blockIdx.x*blockDim.x + threadIdx.x;
    if(i < NN){ g_cnt[i]=0; g_fill[i]=0; }
}
__global__ void k_count(const int* __restrict__ edge){
    int e = blockIdx.x*blockDim.x + threadIdx.x;
    if(e >= ETOT) return;
    int d = (e < E0) ? edge[E0+e] : (e-E0);
    atomicAdd(&g_cnt[d], 1);
}
__global__ void k_scan(){  // 1 block, 1024 threads; 16 nodes per thread
    __shared__ int sums[1024];
    int t = threadIdx.x;
    int base = t*16;
    int loc[16];
    int s = 0;
    #pragma unroll
    for(int i=0;i<16;i++){ loc[i] = s; s += g_cnt[base+i]; }
    sums[t] = s;
    __syncthreads();
    for(int off=1; off<1024; off<<=1){
        int v = 0;
        if(t >= off) v = sums[t-off];
        __syncthreads();
        if(t >= off) sums[t] += v;
        __syncthreads();
    }
    int pre = (t==0) ? 0 : sums[t-1];
    #pragma unroll
    for(int i=0;i<16;i++) g_rowptr[base+i] = pre + loc[i];
    if(t == 1023) g_rowptr[NN] = sums[1023];
}
__global__ void k_scatter(const int* __restrict__ edge){
    int e = blockIdx.x*blockDim.x + threadIdx.x;
    if(e >= ETOT) return;
    int s, d;
    if(e < E0){ s = edge[e]; d = edge[E0+e]; }
    else { s = e-E0; d = s; }
    int pos = g_rowptr[d] + atomicAdd(&g_fill[d], 1);
    g_col[pos] = s;
}

// ---------------- GEMM0: g_h0[N,512] = nodes @ W0 ----------------
// nodes row n = x[n%SEQ, n/SEQ, :]   (x is [SEQ,BSZ,DIM])
// tiles: 128x64, BK=16, 256 threads, 8x4 per thread
__global__ void k_gemm0(const float* __restrict__ x, const float* __restrict__ W0){
    __shared__ float As[16][128];
    __shared__ float Bs[16][64];
    int t = threadIdx.x;
    int tx = t & 15, ty = t >> 4;
    int row0 = blockIdx.y * 128;
    int col0 = blockIdx.x * 64;

    int m  = t >> 1;
    int kb = (t & 1) * 8;            // this thread covers kk kb..kb+7 of row m
    int gm = row0 + m;
    const float* arow = x + (size_t)((gm & (SEQ-1))*BSZ + (gm >> 10)) * DIM;
    int bkk = t >> 4, bn4 = t & 15;

    float acc[8][4];
    #pragma unroll
    for(int i=0;i<8;i++)
        #pragma unroll
        for(int j=0;j<4;j++) acc[i][j]=0.f;

    for(int k0=0; k0<DIM; k0+=16){
        float4 va = *(const float4*)(arow + k0 + kb);
        float4 vb = *(const float4*)(arow + k0 + kb + 4);
        As[kb+0][m]=va.x; As[kb+1][m]=va.y; As[kb+2][m]=va.z; As[kb+3][m]=va.w;
        As[kb+4][m]=vb.x; As[kb+5][m]=vb.y; As[kb+6][m]=vb.z; As[kb+7][m]=vb.w;
        *(float4*)&Bs[bkk][bn4*4] = *(const float4*)(W0 + (size_t)(k0+bkk)*DIM + col0 + bn4*4);
        __syncthreads();
        #pragma unroll
        for(int kk=0;kk<16;kk++){
            float4 b4 = *(float4*)&Bs[kk][tx*4];
            float4 a0 = *(float4*)&As[kk][ty*8];
            float4 a1 = *(float4*)&As[kk][ty*8+4];
            float ar[8] = {a0.x,a0.y,a0.z,a0.w,a1.x,a1.y,a1.z,a1.w};
            float br[4] = {b4.x,b4.y,b4.z,b4.w};
            #pragma unroll
            for(int i=0;i<8;i++)
                #pragma unroll
                for(int j=0;j<4;j++) acc[i][j] += ar[i]*br[j];
        }
        __syncthreads();
    }
    #pragma unroll
    for(int i=0;i<8;i++){
        int gm2 = row0 + ty*8 + i;
        float4 o = make_float4(acc[i][0],acc[i][1],acc[i][2],acc[i][3]);
        *(float4*)&g_h0[(size_t)gm2*DIM + col0 + tx*4] = o;
    }
}

// ---------------- alpha0: per-node per-head dot with att vectors ----------
__global__ void k_alpha0(const float* __restrict__ as0, const float* __restrict__ ad0){
    int n = blockIdx.x;
    int h = threadIdx.x >> 5, lane = threadIdx.x & 31;
    const float* hp = g_h0 + (size_t)n*DIM + h*64;
    float s=0.f, d=0.f;
    #pragma unroll
    for(int k=lane;k<64;k+=32){ float v=hp[k]; s += v*as0[h*64+k]; d += v*ad0[h*64+k]; }
    s = warpSum(s); d = warpSum(d);
    if(lane==0){ g_asrc0[n*NH+h]=s; g_adst0[n*NH+h]=d; }
}

// ---------------- aggregate0: softmax + weighted sum + bias + elu ---------
__global__ void k_agg0(const float* __restrict__ b0){
    int d = blockIdx.x;
    int h = threadIdx.x >> 5, lane = threadIdx.x & 31;
    int start = g_rowptr[d], deg = g_rowptr[d+1]-start;
    float adst = g_adst0[d*NH+h];
    float m = -1e30f;
    for(int i=lane;i<deg;i+=32){ int s=g_col[start+i]; m = fmaxf(m, lrelu(g_asrc0[s*NH+h]+adst)); }
    m = warpMax(m);
    float z = 0.f;
    for(int i=lane;i<deg;i+=32){ int s=g_col[start+i]; z += __expf(lrelu(g_asrc0[s*NH+h]+adst)-m); }
    z = warpSum(z);
    float invz = 1.f/(z + 1e-16f);
    float acc0=0.f, acc1=0.f;
    for(int i=0;i<deg;i++){
        int s = g_col[start+i];
        float w = __expf(lrelu(g_asrc0[s*NH+h]+adst)-m)*invz;
        const float* hp = g_h0 + (size_t)s*DIM + h*64;
        acc0 += w*hp[lane];
        acc1 += w*hp[lane+32];
    }
    int c = h*64 + lane;
    g_h0act[(size_t)d*DIM + c]      = eluf(acc0 + b0[c]);
    g_h0act[(size_t)d*DIM + c + 32] = eluf(acc1 + b0[c+32]);
}

// ---------------- weff1: wsrc[h,k] = sum_c W1[k, h*512+c]*att_src1[h,c] ---
__global__ void k_weff1(const float* __restrict__ W1, const float* __restrict__ as1,
                        const float* __restrict__ ad1){
    int w = blockIdx.x*8 + (threadIdx.x >> 5);
    int lane = threadIdx.x & 31;
    int h = w >> 9, k = w & 511;
    const float* wr = W1 + (size_t)k*(NH*DIM) + h*DIM;
    float s=0.f, d=0.f;
    for(int c=lane;c<DIM;c+=32){ float v=wr[c]; s += v*as1[h*DIM+c]; d += v*ad1[h*DIM+c]; }
    s = warpSum(s); d = warpSum(d);
    if(lane==0){ g_wsrc1[h*DIM+k]=s; g_wdst1[h*DIM+k]=d; }
}

// ---------------- alpha1 -------------------------------------------------
__global__ void k_alpha1(){
    int n = blockIdx.x;
    int h = threadIdx.x >> 5, lane = threadIdx.x & 31;
    const float* hp = g_h0act + (size_t)n*DIM;
    float s=0.f, d=0.f;
    for(int k=lane;k<DIM;k+=32){ float v=hp[k]; s += v*g_wsrc1[h*DIM+k]; d += v*g_wdst1[h*DIM+k]; }
    s = warpSum(s); d = warpSum(d);
    if(lane==0){ g_asrc1[n*NH+h]=s; g_adst1[n*NH+h]=d; }
}

// ---------------- aggregate1: agg[d, h*512+k] = sum_e w[e,h]*h0act[src,k] -
__global__ void k_agg1(){
    __shared__ float v[512];
    __shared__ float ws[8];
    __shared__ float sm[8];
    __shared__ float sinvz[8];
    int d = blockIdx.x;
    int t = threadIdx.x;
    int warp = t >> 5, lane = t & 31;
    int start = g_rowptr[d], deg = g_rowptr[d+1]-start;
    {
        int h = warp;
        float adst = g_adst1[d*NH+h];
        float m = -1e30f;
        for(int i=lane;i<deg;i+=32){ int s=g_col[start+i]; m = fmaxf(m, lrelu(g_asrc1[s*NH+h]+adst)); }
        m = warpMax(m);
        float z = 0.f;
        for(int i=lane;i<deg;i+=32){ int s=g_col[start+i]; z += __expf(lrelu(g_asrc1[s*NH+h]+adst)-m); }
        z = warpSum(z);
        if(lane==0){ sm[h]=m; sinvz[h]=1.f/(z+1e-16f); }
    }
    __syncthreads();
    float acc[8][2];
    #pragma unroll
    for(int h=0;h<8;h++){ acc[h][0]=0.f; acc[h][1]=0.f; }
    float adst_l = (t < 8) ? g_adst1[d*NH+t] : 0.f;
    for(int i=0;i<deg;i++){
        int s = g_col[start+i];
        v[t]     = g_h0act[(size_t)s*DIM + t];
        v[t+256] = g_h0act[(size_t)s*DIM + t + 256];
        if(t < 8) ws[t] = __expf(lrelu(g_asrc1[s*NH+t]+adst_l)-sm[t])*sinvz[t];
        __syncthreads();
        float a0 = v[t], a1 = v[t+256];
        float w[8];
        #pragma unroll
        for(int h=0;h<8;h++) w[h] = ws[h];
        #pragma unroll
        for(int h=0;h<8;h++){ acc[h][0] += w[h]*a0; acc[h][1] += w[h]*a1; }
        __syncthreads();
    }
    float* out = g_agg1 + (size_t)d*(NH*DIM);
    #pragma unroll
    for(int h=0;h<8;h++){
        out[h*DIM + t]       = acc[h][0];
        out[h*DIM + t + 256] = acc[h][1];
    }
}

// ---------------- wcat: Wcat[h*512+k, c] = W1[k, h*512+c]/8 --------------
__global__ void k_wcat(const float* __restrict__ W1){
    int i = blockIdx.x*blockDim.x + threadIdx.x;   // < 4096*512
    int c  = i & 511;
    int kk = i >> 9;          // h*512 + k
    int h = kk >> 9, k = kk & 511;
    g_wcat[i] = W1[(size_t)k*(NH*DIM) + h*DIM + c] * 0.125f;
}

// ---------------- GEMM final: out = elu(agg1 @ Wcat + b1) ----------------
__global__ void k_gemm1(const float* __restrict__ b1, float* __restrict__ out){
    __shared__ float As[16][128];
    __shared__ float Bs[16][64];
    int t = threadIdx.x;
    int tx = t & 15, ty = t >> 4;
    int row0 = blockIdx.y * 128;
    int col0 = blockIdx.x * 64;

    int m  = t >> 1;
    int kb = (t & 1) * 8;
    int gm = row0 + m;
    const float* arow = g_agg1 + (size_t)gm*(NH*DIM);
    int bkk = t >> 4, bn4 = t & 15;

    float acc[8][4];
    #pragma unroll
    for(int i=0;i<8;i++)
        #pragma unroll
        for(int j=0;j<4;j++) acc[i][j]=0.f;

    for(int k0=0; k0<NH*DIM; k0+=16){
        float4 va = *(const float4*)(arow + k0 + kb);
        float4 vb = *(const float4*)(arow + k0 + kb + 4);
        As[kb+0][m]=va.x; As[kb+1][m]=va.y; As[kb+2][m]=va.z; As[kb+3][m]=va.w;
        As[kb+4][m]=vb.x; As[kb+5][m]=vb.y; As[kb+6][m]=vb.z; As[kb+7][m]=vb.w;
        *(float4*)&Bs[bkk][bn4*4] = *(const float4*)(g_wcat + (size_t)(k0+bkk)*DIM + col0 + bn4*4);
        __syncthreads();
        #pragma unroll
        for(int kk=0;kk<16;kk++){
            float4 b4 = *(float4*)&Bs[kk][tx*4];
            float4 a0 = *(float4*)&As[kk][ty*8];
            float4 a1 = *(float4*)&As[kk][ty*8+4];
            float ar[8] = {a0.x,a0.y,a0.z,a0.w,a1.x,a1.y,a1.z,a1.w};
            float br[4] = {b4.x,b4.y,b4.z,b4.w};
            #pragma unroll
            for(int i=0;i<8;i++)
                #pragma unroll
                for(int j=0;j<4;j++) acc[i][j] += ar[i]*br[j];
        }
        __syncthreads();
    }
    int c = col0 + tx*4;
    float4 bb = *(const float4*)(b1 + c);
    #pragma unroll
    for(int i=0;i<8;i++){
        int gm2 = row0 + ty*8 + i;
        float4 o;
        o.x = eluf(acc[i][0] + bb.x);
        o.y = eluf(acc[i][1] + bb.y);
        o.z = eluf(acc[i][2] + bb.z);
        o.w = eluf(acc[i][3] + bb.w);
        *(float4*)&out[(size_t)gm2*DIM + c] = o;   // output reshape = raw reinterpret
    }
}

// ---------------- launch ----------------
extern "C" void kernel_launch(void* const* d_in, const int* in_sizes, int n_in,
                              void* d_out, int out_size){
    const float* x   = (const float*)d_in[0];
    const int*   edge= (const int*)  d_in[1];
    const float* W0  = (const float*)d_in[2];
    const float* as0 = (const float*)d_in[3];
    const float* ad0 = (const float*)d_in[4];
    const float* b0  = (const float*)d_in[5];
    const float* W1  = (const float*)d_in[6];
    const float* as1 = (const float*)d_in[7];
    const float* ad1 = (const float*)d_in[8];
    const float* b1  = (const float*)d_in[9];
    float* out = (float*)d_out;

    k_zero<<<(NN+255)/256, 256>>>();
    k_count<<<(ETOT+255)/256, 256>>>(edge);
    k_scan<<<1, 1024>>>();
    k_scatter<<<(ETOT+255)/256, 256>>>(edge);

    k_gemm0<<<dim3(DIM/64, NN/128), 256>>>(x, W0);
    k_alpha0<<<NN, 256>>>(as0, ad0);
    k_agg0<<<NN, 256>>>(b0);

    k_weff1<<<512, 256>>>(W1, as1, ad1);
    k_alpha1<<<NN, 256>>>();
    k_agg1<<<NN, 256>>>();
    k_wcat<<<(NH*DIM*DIM)/1024, 1024>>>(W1);
    k_gemm1<<<dim3(DIM/64, NN/128), 256>>>(b1, out);
}

// round 13
// speedup vs baseline: 1.0081x; 1.0070x over previous

#include <cuda_runtime.h>
#include <cstdint>

#define SEQ 1024
#define BSZ 16
#define DIM 512
#define NH 8
#define NN (SEQ*BSZ)          // 16384 nodes
#define E0 (NN*32)            // 524288 edges
#define ETOT (E0+NN)          // + self loops

// ---------------- scratch (device globals; accessed ONLY by symbol inside
// kernels — never passed as launch arguments from host code) ----------------
__device__ float g_h0[(size_t)NN*DIM];        // nodes @ W0 (pre-aggregation)
__device__ float g_h0act[(size_t)NN*DIM];     // layer0 output (elu)
__device__ float g_asrc0[NN*NH], g_adst0[NN*NH];
__device__ float g_asrc1[NN*NH], g_adst1[NN*NH];
__device__ float g_wsrc1[NH*DIM], g_wdst1[NH*DIM];
__device__ float g_agg1[(size_t)NN*NH*DIM];   // 268MB: per-head aggregated inputs
__device__ float g_wcat[(size_t)NH*DIM*DIM];  // permuted W1 * 1/8
__device__ int g_cnt[NN], g_fill[NN], g_rowptr[NN+1], g_col[ETOT];

// ---------------- helpers ----------------
__device__ __forceinline__ float lrelu(float v){ return v > 0.f ? v : 0.2f*v; }
__device__ __forceinline__ float eluf(float v){ return v > 0.f ? v : expm1f(v); }
__device__ __forceinline__ float warpMax(float v){
    #pragma unroll
    for(int o=16;o;o>>=1) v = fmaxf(v, __shfl_xor_sync(0xffffffffu, v, o));
    return v;
}
__device__ __forceinline__ float warpSum(float v){
    #pragma unroll
    for(int o=16;o;o>>=1) v += __shfl_xor_sync(0xffffffffu, v, o);
    return v;
}

// ---------------- CSR build ----------------
__global__ void k_zero(){
    int i = blockIdx.x*blockDim.x + threadIdx.x;
    if(i < NN){ g_cnt[i]=0; g_fill[i]=0; }
}
__global__ void k_count(const int* __restrict__ edge){
    int e = blockIdx.x*blockDim.x + threadIdx.x;
    if(e >= ETOT) return;
    int d = (e < E0) ? edge[E0+e] : (e-E0);
    atomicAdd(&g_cnt[d], 1);
}
__global__ void k_scan(){  // 1 block, 1024 threads; 16 nodes per thread
    __shared__ int sums[1024];
    int t = threadIdx.x;
    int base = t*16;
    int loc[16];
    int s = 0;
    #pragma unroll
    for(int i=0;i<16;i++){ loc[i] = s; s += g_cnt[base+i]; }
    sums[t] = s;
    __syncthreads();
    for(int off=1; off<1024; off<<=1){
        int v = 0;
        if(t >= off) v = sums[t-off];
        __syncthreads();
        if(t >= off) sums[t] += v;
        __syncthreads();
    }
    int pre = (t==0) ? 0 : sums[t-1];
    #pragma unroll
    for(int i=0;i<16;i++) g_rowptr[base+i] = pre + loc[i];
    if(t == 1023) g_rowptr[NN] = sums[1023];
}
__global__ void k_scatter(const int* __restrict__ edge){
    int e = blockIdx.x*blockDim.x + threadIdx.x;
    if(e >= ETOT) return;
    int s, d;
    if(e < E0){ s = edge[e]; d = edge[E0+e]; }
    else { s = e-E0; d = s; }
    int pos = g_rowptr[d] + atomicAdd(&g_fill[d], 1);
    g_col[pos] = s;
}

// ---------------- GEMM0: g_h0[N,512] = nodes @ W0 ----------------
// nodes row n = x[n%SEQ, n/SEQ, :]   (x is [SEQ,BSZ,DIM])
// tiles: 128x64, BK=16, 256 threads, 8x4 per thread; register-prefetch
// double buffering (next tile's LDGs issued before the FFMA block).
__global__ void k_gemm0(const float* __restrict__ x, const float* __restrict__ W0){
    __shared__ float As[16][128];
    __shared__ float Bs[16][64];
    int t = threadIdx.x;
    int tx = t & 15, ty = t >> 4;
    int row0 = blockIdx.y * 128;
    int col0 = blockIdx.x * 64;

    int m  = t >> 1;
    int kb = (t & 1) * 8;            // this thread covers kk kb..kb+7 of row m
    int gm = row0 + m;
    const float* arow = x + (size_t)((gm & (SEQ-1))*BSZ + (gm >> 10)) * DIM;
    int bkk = t >> 4, bn4 = t & 15;
    const float* brow = W0 + (size_t)bkk*DIM + col0 + bn4*4;

    float4 pa0 = *(const float4*)(arow + kb);
    float4 pa1 = *(const float4*)(arow + kb + 4);
    float4 pb  = *(const float4*)(brow);

    float acc[8][4];
    #pragma unroll
    for(int i=0;i<8;i++)
        #pragma unroll
        for(int j=0;j<4;j++) acc[i][j]=0.f;

    for(int k0=0; k0<DIM; k0+=16){
        As[kb+0][m]=pa0.x; As[kb+1][m]=pa0.y; As[kb+2][m]=pa0.z; As[kb+3][m]=pa0.w;
        As[kb+4][m]=pa1.x; As[kb+5][m]=pa1.y; As[kb+6][m]=pa1.z; As[kb+7][m]=pa1.w;
        *(float4*)&Bs[bkk][bn4*4] = pb;
        __syncthreads();
        if(k0 + 16 < DIM){
            pa0 = *(const float4*)(arow + k0 + 16 + kb);
            pa1 = *(const float4*)(arow + k0 + 16 + kb + 4);
            pb  = *(const float4*)(brow + (size_t)(k0 + 16)*DIM);
        }
        #pragma unroll
        for(int kk=0;kk<16;kk++){
            float4 b4 = *(float4*)&Bs[kk][tx*4];
            float4 a0 = *(float4*)&As[kk][ty*8];
            float4 a1 = *(float4*)&As[kk][ty*8+4];
            float ar[8] = {a0.x,a0.y,a0.z,a0.w,a1.x,a1.y,a1.z,a1.w};
            float br[4] = {b4.x,b4.y,b4.z,b4.w};
            #pragma unroll
            for(int i=0;i<8;i++)
                #pragma unroll
                for(int j=0;j<4;j++) acc[i][j] += ar[i]*br[j];
        }
        __syncthreads();
    }
    #pragma unroll
    for(int i=0;i<8;i++){
        int gm2 = row0 + ty*8 + i;
        float4 o = make_float4(acc[i][0],acc[i][1],acc[i][2],acc[i][3]);
        *(float4*)&g_h0[(size_t)gm2*DIM + col0 + tx*4] = o;
    }
}

// ---------------- alpha0: per-node per-head dot with att vectors ----------
__global__ void k_alpha0(const float* __restrict__ as0, const float* __restrict__ ad0){
    int n = blockIdx.x;
    int h = threadIdx.x >> 5, lane = threadIdx.x & 31;
    const float* hp = g_h0 + (size_t)n*DIM + h*64;
    float s=0.f, d=0.f;
    #pragma unroll
    for(int k=lane;k<64;k+=32){ float v=hp[k]; s += v*as0[h*64+k]; d += v*ad0[h*64+k]; }
    s = warpSum(s); d = warpSum(d);
    if(lane==0){ g_asrc0[n*NH+h]=s; g_adst0[n*NH+h]=d; }
}

// ---------------- aggregate0: softmax + weighted sum + bias + elu ---------
__global__ void k_agg0(const float* __restrict__ b0){
    __shared__ int cols_s[128];
    int d = blockIdx.x;
    int t = threadIdx.x;
    int h = t >> 5, lane = t & 31;
    int start = g_rowptr[d], deg = g_rowptr[d+1]-start;
    int ncache = deg < 128 ? deg : 128;
    for(int i=t;i<ncache;i+=256) cols_s[i] = g_col[start+i];
    __syncthreads();
    float adst = g_adst0[d*NH+h];
    float m = -1e30f;
    for(int i=lane;i<deg;i+=32){
        int s = (i<128) ? cols_s[i] : g_col[start+i];
        m = fmaxf(m, lrelu(g_asrc0[s*NH+h]+adst));
    }
    m = warpMax(m);
    float z = 0.f;
    for(int i=lane;i<deg;i+=32){
        int s = (i<128) ? cols_s[i] : g_col[start+i];
        z += __expf(lrelu(g_asrc0[s*NH+h]+adst)-m);
    }
    z = warpSum(z);
    float invz = 1.f/(z + 1e-16f);
    float acc0=0.f, acc1=0.f;
    for(int i=0;i<deg;i++){
        int s = (i<128) ? cols_s[i] : g_col[start+i];
        float w = __expf(lrelu(g_asrc0[s*NH+h]+adst)-m)*invz;
        const float* hp = g_h0 + (size_t)s*DIM + h*64;
        acc0 += w*hp[lane];
        acc1 += w*hp[lane+32];
    }
    int c = h*64 + lane;
    g_h0act[(size_t)d*DIM + c]      = eluf(acc0 + b0[c]);
    g_h0act[(size_t)d*DIM + c + 32] = eluf(acc1 + b0[c+32]);
}

// ---------------- weff1: wsrc[h,k] = sum_c W1[k, h*512+c]*att_src1[h,c] ---
__global__ void k_weff1(const float* __restrict__ W1, const float* __restrict__ as1,
                        const float* __restrict__ ad1){
    int w = blockIdx.x*8 + (threadIdx.x >> 5);
    int lane = threadIdx.x & 31;
    int h = w >> 9, k = w & 511;
    const float* wr = W1 + (size_t)k*(NH*DIM) + h*DIM;
    float s=0.f, d=0.f;
    for(int c=lane;c<DIM;c+=32){ float v=wr[c]; s += v*as1[h*DIM+c]; d += v*ad1[h*DIM+c]; }
    s = warpSum(s); d = warpSum(d);
    if(lane==0){ g_wsrc1[h*DIM+k]=s; g_wdst1[h*DIM+k]=d; }
}

// ---------------- alpha1 -------------------------------------------------
__global__ void k_alpha1(){
    int n = blockIdx.x;
    int h = threadIdx.x >> 5, lane = threadIdx.x & 31;
    const float* hp = g_h0act + (size_t)n*DIM;
    float s=0.f, d=0.f;
    for(int k=lane;k<DIM;k+=32){ float v=hp[k]; s += v*g_wsrc1[h*DIM+k]; d += v*g_wdst1[h*DIM+k]; }
    s = warpSum(s); d = warpSum(d);
    if(lane==0){ g_asrc1[n*NH+h]=s; g_adst1[n*NH+h]=d; }
}

// ---------------- aggregate1: agg[d, h*512+k] = sum_e w[e,h]*h0act[src,k] -
__global__ void k_agg1(){
    __shared__ float v[512];
    __shared__ float ws[8];
    __shared__ float sm[8];
    __shared__ float sinvz[8];
    __shared__ int cols_s[128];
    int d = blockIdx.x;
    int t = threadIdx.x;
    int warp = t >> 5, lane = t & 31;
    int start = g_rowptr[d], deg = g_rowptr[d+1]-start;
    int ncache = deg < 128 ? deg : 128;
    for(int i=t;i<ncache;i+=256) cols_s[i] = g_col[start+i];
    __syncthreads();
    {
        int h = warp;
        float adst = g_adst1[d*NH+h];
        float m = -1e30f;
        for(int i=lane;i<deg;i+=32){
            int s = (i<128) ? cols_s[i] : g_col[start+i];
            m = fmaxf(m, lrelu(g_asrc1[s*NH+h]+adst));
        }
        m = warpMax(m);
        float z = 0.f;
        for(int i=lane;i<deg;i+=32){
            int s = (i<128) ? cols_s[i] : g_col[start+i];
            z += __expf(lrelu(g_asrc1[s*NH+h]+adst)-m);
        }
        z = warpSum(z);
        if(lane==0){ sm[h]=m; sinvz[h]=1.f/(z+1e-16f); }
    }
    __syncthreads();
    float acc[8][2];
    #pragma unroll
    for(int h=0;h<8;h++){ acc[h][0]=0.f; acc[h][1]=0.f; }
    float adst_l = (t < 8) ? g_adst1[d*NH+t] : 0.f;
    for(int i=0;i<deg;i++){
        int s = (i<128) ? cols_s[i] : g_col[start+i];
        v[t]     = g_h0act[(size_t)s*DIM + t];
        v[t+256] = g_h0act[(size_t)s*DIM + t + 256];
        if(t < 8) ws[t] = __expf(lrelu(g_asrc1[s*NH+t]+adst_l)-sm[t])*sinvz[t];
        __syncthreads();
        float a0 = v[t], a1 = v[t+256];
        float w[8];
        #pragma unroll
        for(int h=0;h<8;h++) w[h] = ws[h];
        #pragma unroll
        for(int h=0;h<8;h++){ acc[h][0] += w[h]*a0; acc[h][1] += w[h]*a1; }
        __syncthreads();
    }
    float* out = g_agg1 + (size_t)d*(NH*DIM);
    #pragma unroll
    for(int h=0;h<8;h++){
        out[h*DIM + t]       = acc[h][0];
        out[h*DIM + t + 256] = acc[h][1];
    }
}

// ---------------- wcat: Wcat[h*512+k, c] = W1[k, h*512+c]/8 --------------
__global__ void k_wcat(const float* __restrict__ W1){
    int i = blockIdx.x*blockDim.x + threadIdx.x;   // < 4096*512
    int c  = i & 511;
    int kk = i >> 9;          // h*512 + k
    int h = kk >> 9, k = kk & 511;
    g_wcat[i] = W1[(size_t)k*(NH*DIM) + h*DIM + c] * 0.125f;
}

// ---------------- GEMM final: out = elu(agg1 @ Wcat + b1) ----------------
// same prefetch double buffering as k_gemm0
__global__ void k_gemm1(const float* __restrict__ b1, float* __restrict__ out){
    __shared__ float As[16][128];
    __shared__ float Bs[16][64];
    int t = threadIdx.x;
    int tx = t & 15, ty = t >> 4;
    int row0 = blockIdx.y * 128;
    int col0 = blockIdx.x * 64;

    int m  = t >> 1;
    int kb = (t & 1) * 8;
    int gm = row0 + m;
    const float* arow = g_agg1 + (size_t)gm*(NH*DIM);
    int bkk = t >> 4, bn4 = t & 15;
    const float* brow = g_wcat + (size_t)bkk*DIM + col0 + bn4*4;

    float4 pa0 = *(const float4*)(arow + kb);
    float4 pa1 = *(const float4*)(arow + kb + 4);
    float4 pb  = *(const float4*)(brow);

    float acc[8][4];
    #pragma unroll
    for(int i=0;i<8;i++)
        #pragma unroll
        for(int j=0;j<4;j++) acc[i][j]=0.f;

    for(int k0=0; k0<NH*DIM; k0+=16){
        As[kb+0][m]=pa0.x; As[kb+1][m]=pa0.y; As[kb+2][m]=pa0.z; As[kb+3][m]=pa0.w;
        As[kb+4][m]=pa1.x; As[kb+5][m]=pa1.y; As[kb+6][m]=pa1.z; As[kb+7][m]=pa1.w;
        *(float4*)&Bs[bkk][bn4*4] = pb;
        __syncthreads();
        if(k0 + 16 < NH*DIM){
            pa0 = *(const float4*)(arow + k0 + 16 + kb);
            pa1 = *(const float4*)(arow + k0 + 16 + kb + 4);
            pb  = *(const float4*)(brow + (size_t)(k0 + 16)*DIM);
        }
        #pragma unroll
        for(int kk=0;kk<16;kk++){
            float4 b4 = *(float4*)&Bs[kk][tx*4];
            float4 a0 = *(float4*)&As[kk][ty*8];
            float4 a1 = *(float4*)&As[kk][ty*8+4];
            float ar[8] = {a0.x,a0.y,a0.z,a0.w,a1.x,a1.y,a1.z,a1.w};
            float br[4] = {b4.x,b4.y,b4.z,b4.w};
            #pragma unroll
            for(int i=0;i<8;i++)
                #pragma unroll
                for(int j=0;j<4;j++) acc[i][j] += ar[i]*br[j];
        }
        __syncthreads();
    }
    int c = col0 + tx*4;
    float4 bb = *(const float4*)(b1 + c);
    #pragma unroll
    for(int i=0;i<8;i++){
        int gm2 = row0 + ty*8 + i;
        float4 o;
        o.x = eluf(acc[i][0] + bb.x);
        o.y = eluf(acc[i][1] + bb.y);
        o.z = eluf(acc[i][2] + bb.z);
        o.w = eluf(acc[i][3] + bb.w);
        *(float4*)&out[(size_t)gm2*DIM + c] = o;   // output reshape = raw reinterpret
    }
}

// ---------------- launch ----------------
extern "C" void kernel_launch(void* const* d_in, const int* in_sizes, int n_in,
                              void* d_out, int out_size){
    const float* x   = (const float*)d_in[0];
    const int*   edge= (const int*)  d_in[1];
    const float* W0  = (const float*)d_in[2];
    const float* as0 = (const float*)d_in[3];
    const float* ad0 = (const float*)d_in[4];
    const float* b0  = (const float*)d_in[5];
    const float* W1  = (const float*)d_in[6];
    const float* as1 = (const float*)d_in[7];
    const float* ad1 = (const float*)d_in[8];
    const float* b1  = (const float*)d_in[9];
    float* out = (float*)d_out;

    k_zero<<<(NN+255)/256, 256>>>();
    k_count<<<(ETOT+255)/256, 256>>>(edge);
    k_scan<<<1, 1024>>>();
    k_scatter<<<(ETOT+255)/256, 256>>>(edge);

    k_gemm0<<<dim3(DIM/64, NN/128), 256>>>(x, W0);
    k_alpha0<<<NN, 256>>>(as0, ad0);
    k_agg0<<<NN, 256>>>(b0);

    k_weff1<<<512, 256>>>(W1, as1, ad1);
    k_alpha1<<<NN, 256>>>();
    k_agg1<<<NN, 256>>>();
    k_wcat<<<(NH*DIM*DIM)/1024, 1024>>>(W1);
    k_gemm1<<<dim3(DIM/64, NN/128), 256>>>(b1, out);
}

// round 14
// speedup vs baseline: 1.4972x; 1.4851x over previous

#include <cuda_runtime.h>
#include <cstdint>

#define SEQ 1024
#define BSZ 16
#define DIM 512
#define NH 8
#define NN (SEQ*BSZ)          // 16384 nodes
#define E0 (NN*32)            // 524288 edges
#define ETOT (E0+NN)          // + self loops

// ---------------- scratch (device globals; accessed ONLY by symbol inside
// kernels — never passed as launch arguments from host code) ----------------
__device__ float g_h0[(size_t)NN*DIM];        // nodes @ W0 (pre-aggregation)
__device__ float g_h0act[(size_t)NN*DIM];     // layer0 output (elu)
__device__ float g_asrc0[NN*NH], g_adst0[NN*NH];
__device__ float g_asrc1[NN*NH], g_adst1[NN*NH];
__device__ float g_wsrc1[NH*DIM], g_wdst1[NH*DIM];
__device__ float g_agg1[(size_t)NN*NH*DIM];   // per-head aggregated inputs (tf32-rounded)
__device__ float g_wcat[(size_t)NH*DIM*DIM];  // tf32-rounded permuted W1 * 1/8
__device__ int g_cnt[NN], g_fill[NN], g_rowptr[NN+1], g_col[ETOT];

// ---------------- helpers ----------------
__device__ __forceinline__ float lrelu(float v){ return v > 0.f ? v : 0.2f*v; }
__device__ __forceinline__ float eluf(float v){ return v > 0.f ? v : expm1f(v); }
__device__ __forceinline__ float warpMax(float v){
    #pragma unroll
    for(int o=16;o;o>>=1) v = fmaxf(v, __shfl_xor_sync(0xffffffffu, v, o));
    return v;
}
__device__ __forceinline__ float warpSum(float v){
    #pragma unroll
    for(int o=16;o;o>>=1) v += __shfl_xor_sync(0xffffffffu, v, o);
    return v;
}
// tf32 round-to-nearest in pure C (no asm)
__device__ __forceinline__ float rnaf(float x){
    uint32_t u = __float_as_uint(x);
    u = (u + 0x1000u) & 0xFFFFE000u;
    return __uint_as_float(u);
}
// The ONLY inline asm in this file.
#define MMA_TF32(C0,C1,C2,C3,A0,A1,A2,A3,B0,B1)                               \
    asm volatile(                                                             \
        "mma.sync.aligned.m16n8k8.row.col.f32.tf32.tf32.f32 "                 \
        "{%0,%1,%2,%3}, {%4,%5,%6,%7}, {%8,%9}, {%0,%1,%2,%3};\n"             \
        : "+f"(C0),"+f"(C1),"+f"(C2),"+f"(C3)                                 \
        : "r"(A0),"r"(A1),"r"(A2),"r"(A3), "r"(B0),"r"(B1))

// ---------------- CSR build ----------------
__global__ void k_zero(){
    int i = blockIdx.x*blockDim.x + threadIdx.x;
    if(i < NN){ g_cnt[i]=0; g_fill[i]=0; }
}
__global__ void k_count(const int* __restrict__ edge){
    int e = blockIdx.x*blockDim.x + threadIdx.x;
    if(e >= ETOT) return;
    int d = (e < E0) ? edge[E0+e] : (e-E0);
    atomicAdd(&g_cnt[d], 1);
}
__global__ void k_scan(){  // 1 block, 1024 threads; 16 nodes per thread
    __shared__ int sums[1024];
    int t = threadIdx.x;
    int base = t*16;
    int loc[16];
    int s = 0;
    #pragma unroll
    for(int i=0;i<16;i++){ loc[i] = s; s += g_cnt[base+i]; }
    sums[t] = s;
    __syncthreads();
    for(int off=1; off<1024; off<<=1){
        int v = 0;
        if(t >= off) v = sums[t-off];
        __syncthreads();
        if(t >= off) sums[t] += v;
        __syncthreads();
    }
    int pre = (t==0) ? 0 : sums[t-1];
    #pragma unroll
    for(int i=0;i<16;i++) g_rowptr[base+i] = pre + loc[i];
    if(t == 1023) g_rowptr[NN] = sums[1023];
}
__global__ void k_scatter(const int* __restrict__ edge){
    int e = blockIdx.x*blockDim.x + threadIdx.x;
    if(e >= ETOT) return;
    int s, d;
    if(e < E0){ s = edge[e]; d = edge[E0+e]; }
    else { s = e-E0; d = s; }
    int pos = g_rowptr[d] + atomicAdd(&g_fill[d], 1);
    g_col[pos] = s;
}

// =====================================================================
// tf32 mma.sync GEMM (round-7 proven fragment layout):
//   C[M,512] = A[M,KD] @ B[KD,512]; block 128x64, BK=16, 256 threads,
//   8 warps = 4(M) x 2(N), warp tile 32x32, 32 named-scalar accums.
//   Single-buffer staging; device globals by symbol only.
// =====================================================================
#define DECLC(mi,ni) float c##mi##ni##_0=0.f, c##mi##ni##_1=0.f, \
                           c##mi##ni##_2=0.f, c##mi##ni##_3=0.f
#define NSTEP(k8,ni) { \
    const int n_ = wn + ni*8 + (lane>>2); \
    const uint32_t b0_ = __float_as_uint(Bs[(k8)+(lane&3)    ][n_]); \
    const uint32_t b1_ = __float_as_uint(Bs[(k8)+(lane&3) + 4][n_]); \
    MMA_TF32(c0##ni##_0,c0##ni##_1,c0##ni##_2,c0##ni##_3, a00,a01,a02,a03, b0_,b1_); \
    MMA_TF32(c1##ni##_0,c1##ni##_1,c1##ni##_2,c1##ni##_3, a10,a11,a12,a13, b0_,b1_); }
#define KSTEP(k8) { \
    const int r_  = wm + (lane>>2); \
    const int kk_ = (k8) + (lane&3); \
    const uint32_t a00 = __float_as_uint(As[kk_  ][r_   ]); \
    const uint32_t a01 = __float_as_uint(As[kk_  ][r_+ 8]); \
    const uint32_t a02 = __float_as_uint(As[kk_+4][r_   ]); \
    const uint32_t a03 = __float_as_uint(As[kk_+4][r_+ 8]); \
    const uint32_t a10 = __float_as_uint(As[kk_  ][r_+16]); \
    const uint32_t a11 = __float_as_uint(As[kk_  ][r_+24]); \
    const uint32_t a12 = __float_as_uint(As[kk_+4][r_+16]); \
    const uint32_t a13 = __float_as_uint(As[kk_+4][r_+24]); \
    NSTEP(k8,0) NSTEP(k8,1) NSTEP(k8,2) NSTEP(k8,3) }

// GEMM0: g_h0 = perm(x) @ W0 — raw inputs tf32-rounded during staging.
__global__ void k_gemm0mma(const float* __restrict__ x, const float* __restrict__ W0){
    __shared__ float As[16][136];   // stride 136 = 8 mod 32
    __shared__ float Bs[16][72];    // stride 72  = 8 mod 32
    const int t = threadIdx.x;
    const int lane = t & 31, warp = t >> 5;
    const int row0 = blockIdx.y * 128;
    const int col0 = blockIdx.x * 64;
    const int wm = (warp >> 1) * 32;
    const int wn = (warp & 1) * 32;
    const int m_  = t >> 1;
    const int kb_ = (t & 1) * 8;
    const int gm = row0 + m_;
    const float* arow = x + (size_t)((gm & (SEQ-1))*BSZ + (gm >> 10)) * DIM;
    const int bkr = t >> 4, bn4 = t & 15;

    DECLC(0,0); DECLC(0,1); DECLC(0,2); DECLC(0,3);
    DECLC(1,0); DECLC(1,1); DECLC(1,2); DECLC(1,3);

    for(int k0=0; k0<DIM; k0+=16){
        float4 va = *(const float4*)(arow + k0 + kb_);
        float4 vb = *(const float4*)(arow + k0 + kb_ + 4);
        As[kb_+0][m_]=rnaf(va.x); As[kb_+1][m_]=rnaf(va.y);
        As[kb_+2][m_]=rnaf(va.z); As[kb_+3][m_]=rnaf(va.w);
        As[kb_+4][m_]=rnaf(vb.x); As[kb_+5][m_]=rnaf(vb.y);
        As[kb_+6][m_]=rnaf(vb.z); As[kb_+7][m_]=rnaf(vb.w);
        float4 wv = *(const float4*)(W0 + (size_t)(k0+bkr)*DIM + col0 + bn4*4);
        Bs[bkr][bn4*4+0]=rnaf(wv.x); Bs[bkr][bn4*4+1]=rnaf(wv.y);
        Bs[bkr][bn4*4+2]=rnaf(wv.z); Bs[bkr][bn4*4+3]=rnaf(wv.w);
        __syncthreads();
        KSTEP(0)
        KSTEP(8)
        __syncthreads();
    }
    {
        const int gr0 = row0 + wm + (lane>>2);
        const int gc0 = col0 + wn + 2*(lane&3);
        g_h0[(size_t)gr0*DIM      + gc0    ] = c00_0;
        g_h0[(size_t)gr0*DIM      + gc0 + 1] = c00_1;
        g_h0[(size_t)(gr0+8)*DIM  + gc0    ] = c00_2;
        g_h0[(size_t)(gr0+8)*DIM  + gc0 + 1] = c00_3;
        g_h0[(size_t)gr0*DIM      + gc0+8  ] = c01_0;
        g_h0[(size_t)gr0*DIM      + gc0+9  ] = c01_1;
        g_h0[(size_t)(gr0+8)*DIM  + gc0+8  ] = c01_2;
        g_h0[(size_t)(gr0+8)*DIM  + gc0+9  ] = c01_3;
        g_h0[(size_t)gr0*DIM      + gc0+16 ] = c02_0;
        g_h0[(size_t)gr0*DIM      + gc0+17 ] = c02_1;
        g_h0[(size_t)(gr0+8)*DIM  + gc0+16 ] = c02_2;
        g_h0[(size_t)(gr0+8)*DIM  + gc0+17 ] = c02_3;
        g_h0[(size_t)gr0*DIM      + gc0+24 ] = c03_0;
        g_h0[(size_t)gr0*DIM      + gc0+25 ] = c03_1;
        g_h0[(size_t)(gr0+8)*DIM  + gc0+24 ] = c03_2;
        g_h0[(size_t)(gr0+8)*DIM  + gc0+25 ] = c03_3;
        const int gr1 = gr0 + 16;
        g_h0[(size_t)gr1*DIM      + gc0    ] = c10_0;
        g_h0[(size_t)gr1*DIM      + gc0 + 1] = c10_1;
        g_h0[(size_t)(gr1+8)*DIM  + gc0    ] = c10_2;
        g_h0[(size_t)(gr1+8)*DIM  + gc0 + 1] = c10_3;
        g_h0[(size_t)gr1*DIM      + gc0+8  ] = c11_0;
        g_h0[(size_t)gr1*DIM      + gc0+9  ] = c11_1;
        g_h0[(size_t)(gr1+8)*DIM  + gc0+8  ] = c11_2;
        g_h0[(size_t)(gr1+8)*DIM  + gc0+9  ] = c11_3;
        g_h0[(size_t)gr1*DIM      + gc0+16 ] = c12_0;
        g_h0[(size_t)gr1*DIM      + gc0+17 ] = c12_1;
        g_h0[(size_t)(gr1+8)*DIM  + gc0+16 ] = c12_2;
        g_h0[(size_t)(gr1+8)*DIM  + gc0+17 ] = c12_3;
        g_h0[(size_t)gr1*DIM      + gc0+24 ] = c13_0;
        g_h0[(size_t)gr1*DIM      + gc0+25 ] = c13_1;
        g_h0[(size_t)(gr1+8)*DIM  + gc0+24 ] = c13_2;
        g_h0[(size_t)(gr1+8)*DIM  + gc0+25 ] = c13_3;
    }
}

// GEMM1: out = elu(g_agg1 @ g_wcat + b1) — operands pre-rounded by producers.
__global__ void k_gemm1mma(const float* __restrict__ b1, float* __restrict__ out){
    __shared__ float As[16][136];
    __shared__ float Bs[16][72];
    const int t = threadIdx.x;
    const int lane = t & 31, warp = t >> 5;
    const int row0 = blockIdx.y * 128;
    const int col0 = blockIdx.x * 64;
    const int wm = (warp >> 1) * 32;
    const int wn = (warp & 1) * 32;
    const int m_  = t >> 1;
    const int kb_ = (t & 1) * 8;
    const int gm = row0 + m_;
    const float* arow = g_agg1 + (size_t)gm * (NH*DIM);
    const int bkr = t >> 4, bn4 = t & 15;

    DECLC(0,0); DECLC(0,1); DECLC(0,2); DECLC(0,3);
    DECLC(1,0); DECLC(1,1); DECLC(1,2); DECLC(1,3);

    for(int k0=0; k0<NH*DIM; k0+=16){
        float4 va = *(const float4*)(arow + k0 + kb_);
        float4 vb = *(const float4*)(arow + k0 + kb_ + 4);
        As[kb_+0][m_]=va.x; As[kb_+1][m_]=va.y;
        As[kb_+2][m_]=va.z; As[kb_+3][m_]=va.w;
        As[kb_+4][m_]=vb.x; As[kb_+5][m_]=vb.y;
        As[kb_+6][m_]=vb.z; As[kb_+7][m_]=vb.w;
        float4 wv = *(const float4*)(g_wcat + (size_t)(k0+bkr)*DIM + col0 + bn4*4);
        *(float4*)&Bs[bkr][bn4*4] = wv;
        __syncthreads();
        KSTEP(0)
        KSTEP(8)
        __syncthreads();
    }
#define EPI1(mi,ni) { \
    const int gr_ = row0 + wm + mi*16 + (lane>>2); \
    const int gc_ = col0 + wn + ni*8 + 2*(lane&3); \
    const float bx_ = b1[gc_], by_ = b1[gc_+1]; \
    out[(size_t)gr_*DIM + gc_    ] = eluf(c##mi##ni##_0 + bx_); \
    out[(size_t)gr_*DIM + gc_ + 1] = eluf(c##mi##ni##_1 + by_); \
    out[(size_t)(gr_+8)*DIM + gc_    ] = eluf(c##mi##ni##_2 + bx_); \
    out[(size_t)(gr_+8)*DIM + gc_ + 1] = eluf(c##mi##ni##_3 + by_); }
    EPI1(0,0) EPI1(0,1) EPI1(0,2) EPI1(0,3)
    EPI1(1,0) EPI1(1,1) EPI1(1,2) EPI1(1,3)
#undef EPI1
}

// ---------------- alpha0: per-node per-head dot with att vectors ----------
__global__ void k_alpha0(const float* __restrict__ as0, const float* __restrict__ ad0){
    int n = blockIdx.x;
    int h = threadIdx.x >> 5, lane = threadIdx.x & 31;
    const float* hp = g_h0 + (size_t)n*DIM + h*64;
    float s=0.f, d=0.f;
    #pragma unroll
    for(int k=lane;k<64;k+=32){ float v=hp[k]; s += v*as0[h*64+k]; d += v*ad0[h*64+k]; }
    s = warpSum(s); d = warpSum(d);
    if(lane==0){ g_asrc0[n*NH+h]=s; g_adst0[n*NH+h]=d; }
}

// ---------------- aggregate0: softmax + weighted sum + bias + elu ---------
__global__ void k_agg0(const float* __restrict__ b0){
    __shared__ int cols_s[128];
    int d = blockIdx.x;
    int t = threadIdx.x;
    int h = t >> 5, lane = t & 31;
    int start = g_rowptr[d], deg = g_rowptr[d+1]-start;
    int ncache = deg < 128 ? deg : 128;
    for(int i=t;i<ncache;i+=256) cols_s[i] = g_col[start+i];
    __syncthreads();
    float adst = g_adst0[d*NH+h];
    float m = -1e30f;
    for(int i=lane;i<deg;i+=32){
        int s = (i<128) ? cols_s[i] : g_col[start+i];
        m = fmaxf(m, lrelu(g_asrc0[s*NH+h]+adst));
    }
    m = warpMax(m);
    float z = 0.f;
    for(int i=lane;i<deg;i+=32){
        int s = (i<128) ? cols_s[i] : g_col[start+i];
        z += __expf(lrelu(g_asrc0[s*NH+h]+adst)-m);
    }
    z = warpSum(z);
    float invz = 1.f/(z + 1e-16f);
    float acc0=0.f, acc1=0.f;
    for(int i=0;i<deg;i++){
        int s = (i<128) ? cols_s[i] : g_col[start+i];
        float w = __expf(lrelu(g_asrc0[s*NH+h]+adst)-m)*invz;
        const float* hp = g_h0 + (size_t)s*DIM + h*64;
        acc0 += w*hp[lane];
        acc1 += w*hp[lane+32];
    }
    int c = h*64 + lane;
    g_h0act[(size_t)d*DIM + c]      = eluf(acc0 + b0[c]);
    g_h0act[(size_t)d*DIM + c + 32] = eluf(acc1 + b0[c+32]);
}

// ---------------- weff1: wsrc[h,k] = sum_c W1[k, h*512+c]*att_src1[h,c] ---
__global__ void k_weff1(const float* __restrict__ W1, const float* __restrict__ as1,
                        const float* __restrict__ ad1){
    int w = blockIdx.x*8 + (threadIdx.x >> 5);
    int lane = threadIdx.x & 31;
    int h = w >> 9, k = w & 511;
    const float* wr = W1 + (size_t)k*(NH*DIM) + h*DIM;
    float s=0.f, d=0.f;
    for(int c=lane;c<DIM;c+=32){ float v=wr[c]; s += v*as1[h*DIM+c]; d += v*ad1[h*DIM+c]; }
    s = warpSum(s); d = warpSum(d);
    if(lane==0){ g_wsrc1[h*DIM+k]=s; g_wdst1[h*DIM+k]=d; }
}

// ---------------- alpha1 -------------------------------------------------
__global__ void k_alpha1(){
    int n = blockIdx.x;
    int h = threadIdx.x >> 5, lane = threadIdx.x & 31;
    const float* hp = g_h0act + (size_t)n*DIM;
    float s=0.f, d=0.f;
    for(int k=lane;k<DIM;k+=32){ float v=hp[k]; s += v*g_wsrc1[h*DIM+k]; d += v*g_wdst1[h*DIM+k]; }
    s = warpSum(s); d = warpSum(d);
    if(lane==0){ g_asrc1[n*NH+h]=s; g_adst1[n*NH+h]=d; }
}

// ---------------- aggregate1: agg[d, h*512+k] = sum_e w[e,h]*h0act[src,k] -
// output tf32-rounded (feeds the mma GEMM)
__global__ void k_agg1(){
    __shared__ float v[512];
    __shared__ float ws[8];
    __shared__ float sm[8];
    __shared__ float sinvz[8];
    __shared__ int cols_s[128];
    int d = blockIdx.x;
    int t = threadIdx.x;
    int warp = t >> 5, lane = t & 31;
    int start = g_rowptr[d], deg = g_rowptr[d+1]-start;
    int ncache = deg < 128 ? deg : 128;
    for(int i=t;i<ncache;i+=256) cols_s[i] = g_col[start+i];
    __syncthreads();
    {
        int h = warp;
        float adst = g_adst1[d*NH+h];
        float m = -1e30f;
        for(int i=lane;i<deg;i+=32){
            int s = (i<128) ? cols_s[i] : g_col[start+i];
            m = fmaxf(m, lrelu(g_asrc1[s*NH+h]+adst));
        }
        m = warpMax(m);
        float z = 0.f;
        for(int i=lane;i<deg;i+=32){
            int s = (i<128) ? cols_s[i] : g_col[start+i];
            z += __expf(lrelu(g_asrc1[s*NH+h]+adst)-m);
        }
        z = warpSum(z);
        if(lane==0){ sm[h]=m; sinvz[h]=1.f/(z+1e-16f); }
    }
    __syncthreads();
    float acc[8][2];
    #pragma unroll
    for(int h=0;h<8;h++){ acc[h][0]=0.f; acc[h][1]=0.f; }
    float adst_l = (t < 8) ? g_adst1[d*NH+t] : 0.f;
    for(int i=0;i<deg;i++){
        int s = (i<128) ? cols_s[i] : g_col[start+i];
        v[t]     = g_h0act[(size_t)s*DIM + t];
        v[t+256] = g_h0act[(size_t)s*DIM + t + 256];
        if(t < 8) ws[t] = __expf(lrelu(g_asrc1[s*NH+t]+adst_l)-sm[t])*sinvz[t];
        __syncthreads();
        float a0 = v[t], a1 = v[t+256];
        float w[8];
        #pragma unroll
        for(int h=0;h<8;h++) w[h] = ws[h];
        #pragma unroll
        for(int h=0;h<8;h++){ acc[h][0] += w[h]*a0; acc[h][1] += w[h]*a1; }
        __syncthreads();
    }
    float* outp = g_agg1 + (size_t)d*(NH*DIM);
    #pragma unroll
    for(int h=0;h<8;h++){
        outp[h*DIM + t]       = rnaf(acc[h][0]);
        outp[h*DIM + t + 256] = rnaf(acc[h][1]);
    }
}

// ---------------- wcat: Wcat[h*512+k, c] = rnaf(W1[k, h*512+c]/8) --------
__global__ void k_wcat(const float* __restrict__ W1){
    int i = blockIdx.x*blockDim.x + threadIdx.x;   // < 4096*512
    int c  = i & 511;
    int kk = i >> 9;          // h*512 + k
    int h = kk >> 9, k = kk & 511;
    g_wcat[i] = rnaf(W1[(size_t)k*(NH*DIM) + h*DIM + c] * 0.125f);
}

// ---------------- launch ----------------
extern "C" void kernel_launch(void* const* d_in, const int* in_sizes, int n_in,
                              void* d_out, int out_size){
    const float* x   = (const float*)d_in[0];
    const int*   edge= (const int*)  d_in[1];
    const float* W0  = (const float*)d_in[2];
    const float* as0 = (const float*)d_in[3];
    const float* ad0 = (const float*)d_in[4];
    const float* b0  = (const float*)d_in[5];
    const float* W1  = (const float*)d_in[6];
    const float* as1 = (const float*)d_in[7];
    const float* ad1 = (const float*)d_in[8];
    const float* b1  = (const float*)d_in[9];
    float* out = (float*)d_out;

    k_zero<<<(NN+255)/256, 256>>>();
    k_count<<<(ETOT+255)/256, 256>>>(edge);
    k_scan<<<1, 1024>>>();
    k_scatter<<<(ETOT+255)/256, 256>>>(edge);

    // layer 0: tf32 mma GEMM (rounds inputs in staging) + aggregate
    k_gemm0mma<<<dim3(DIM/64, NN/128), 256>>>(x, W0);
    k_alpha0<<<NN, 256>>>(as0, ad0);
    k_agg0<<<NN, 256>>>(b0);

    // layer 1: alpha via precomposed weights, aggregate, then one big GEMM
    k_weff1<<<512, 256>>>(W1, as1, ad1);
    k_alpha1<<<NN, 256>>>();
    k_agg1<<<NN, 256>>>();
    k_wcat<<<(NH*DIM*DIM)/1024, 1024>>>(W1);
    k_gemm1mma<<<dim3(DIM/64, NN/128), 256>>>(b1, out);
}

// round 15
// speedup vs baseline: 1.6118x; 1.0766x over previous

#include <cuda_runtime.h>
#include <cstdint>

#define SEQ 1024
#define BSZ 16
#define DIM 512
#define NH 8
#define NN (SEQ*BSZ)          // 16384 nodes
#define E0 (NN*32)            // 524288 edges
#define ETOT (E0+NN)          // + self loops

// ---------------- scratch (device globals; accessed ONLY by symbol inside
// kernels — never passed as launch arguments from host code) ----------------
__device__ float g_h0[(size_t)NN*DIM];        // nodes @ W0 (pre-aggregation)
__device__ float g_h0act[(size_t)NN*DIM];     // layer0 output (elu)
__device__ float g_asrc0[NN*NH], g_adst0[NN*NH];
__device__ float g_asrc1[NN*NH], g_adst1[NN*NH];
__device__ float g_wsrc1[NH*DIM], g_wdst1[NH*DIM];
__device__ float g_agg1[(size_t)NN*NH*DIM];   // per-head aggregated inputs (tf32-rounded)
__device__ float g_wcat[(size_t)NH*DIM*DIM];  // tf32-rounded permuted W1 * 1/8
__device__ int g_cnt[NN], g_fill[NN], g_rowptr[NN+1], g_col[ETOT];

// ---------------- helpers ----------------
__device__ __forceinline__ float lrelu(float v){ return v > 0.f ? v : 0.2f*v; }
__device__ __forceinline__ float eluf(float v){ return v > 0.f ? v : expm1f(v); }
__device__ __forceinline__ float warpMax(float v){
    #pragma unroll
    for(int o=16;o;o>>=1) v = fmaxf(v, __shfl_xor_sync(0xffffffffu, v, o));
    return v;
}
__device__ __forceinline__ float warpSum(float v){
    #pragma unroll
    for(int o=16;o;o>>=1) v += __shfl_xor_sync(0xffffffffu, v, o);
    return v;
}
// tf32 round-to-nearest in pure C (no asm)
__device__ __forceinline__ float rnaf(float x){
    uint32_t u = __float_as_uint(x);
    u = (u + 0x1000u) & 0xFFFFE000u;
    return __uint_as_float(u);
}
// The ONLY inline asm in this file.
#define MMA_TF32(C0,C1,C2,C3,A0,A1,A2,A3,B0,B1)                               \
    asm volatile(                                                             \
        "mma.sync.aligned.m16n8k8.row.col.f32.tf32.tf32.f32 "                 \
        "{%0,%1,%2,%3}, {%4,%5,%6,%7}, {%8,%9}, {%0,%1,%2,%3};\n"             \
        : "+f"(C0),"+f"(C1),"+f"(C2),"+f"(C3)                                 \
        : "r"(A0),"r"(A1),"r"(A2),"r"(A3), "r"(B0),"r"(B1))

// ---------------- CSR build ----------------
__global__ void k_zero(){
    int i = blockIdx.x*blockDim.x + threadIdx.x;
    if(i < NN){ g_cnt[i]=0; g_fill[i]=0; }
}
__global__ void k_count(const int* __restrict__ edge){
    int e = blockIdx.x*blockDim.x + threadIdx.x;
    if(e >= ETOT) return;
    int d = (e < E0) ? edge[E0+e] : (e-E0);
    atomicAdd(&g_cnt[d], 1);
}
__global__ void k_scan(){  // 1 block, 1024 threads; 16 nodes per thread
    __shared__ int sums[1024];
    int t = threadIdx.x;
    int base = t*16;
    int loc[16];
    int s = 0;
    #pragma unroll
    for(int i=0;i<16;i++){ loc[i] = s; s += g_cnt[base+i]; }
    sums[t] = s;
    __syncthreads();
    for(int off=1; off<1024; off<<=1){
        int v = 0;
        if(t >= off) v = sums[t-off];
        __syncthreads();
        if(t >= off) sums[t] += v;
        __syncthreads();
    }
    int pre = (t==0) ? 0 : sums[t-1];
    #pragma unroll
    for(int i=0;i<16;i++) g_rowptr[base+i] = pre + loc[i];
    if(t == 1023) g_rowptr[NN] = sums[1023];
}
__global__ void k_scatter(const int* __restrict__ edge){
    int e = blockIdx.x*blockDim.x + threadIdx.x;
    if(e >= ETOT) return;
    int s, d;
    if(e < E0){ s = edge[e]; d = edge[E0+e]; }
    else { s = e-E0; d = s; }
    int pos = g_rowptr[d] + atomicAdd(&g_fill[d], 1);
    g_col[pos] = s;
}

// =====================================================================
// tf32 mma.sync GEMM, block 128x128, BK=16, 256 threads,
//   8 warps = 4(M) x 2(N), warp tile 32x64 -> 64 named-scalar accums.
//   Register-prefetch double buffering on the staging loads.
// =====================================================================
#define DECLC(mi,ni) float c##mi##ni##_0=0.f, c##mi##ni##_1=0.f, \
                           c##mi##ni##_2=0.f, c##mi##ni##_3=0.f
#define NSTEP(k8,ni) { \
    const int n_ = wn + ni*8 + (lane>>2); \
    const uint32_t b0_ = __float_as_uint(Bs[(k8)+(lane&3)    ][n_]); \
    const uint32_t b1_ = __float_as_uint(Bs[(k8)+(lane&3) + 4][n_]); \
    MMA_TF32(c0##ni##_0,c0##ni##_1,c0##ni##_2,c0##ni##_3, a00,a01,a02,a03, b0_,b1_); \
    MMA_TF32(c1##ni##_0,c1##ni##_1,c1##ni##_2,c1##ni##_3, a10,a11,a12,a13, b0_,b1_); }
#define KSTEP(k8) { \
    const int r_  = wm + (lane>>2); \
    const int kk_ = (k8) + (lane&3); \
    const uint32_t a00 = __float_as_uint(As[kk_  ][r_   ]); \
    const uint32_t a01 = __float_as_uint(As[kk_  ][r_+ 8]); \
    const uint32_t a02 = __float_as_uint(As[kk_+4][r_   ]); \
    const uint32_t a03 = __float_as_uint(As[kk_+4][r_+ 8]); \
    const uint32_t a10 = __float_as_uint(As[kk_  ][r_+16]); \
    const uint32_t a11 = __float_as_uint(As[kk_  ][r_+24]); \
    const uint32_t a12 = __float_as_uint(As[kk_+4][r_+16]); \
    const uint32_t a13 = __float_as_uint(As[kk_+4][r_+24]); \
    NSTEP(k8,0) NSTEP(k8,1) NSTEP(k8,2) NSTEP(k8,3) \
    NSTEP(k8,4) NSTEP(k8,5) NSTEP(k8,6) NSTEP(k8,7) }

// GEMM0: g_h0 = perm(x) @ W0 — raw inputs tf32-rounded during staging.
__global__ void k_gemm0mma(const float* __restrict__ x, const float* __restrict__ W0){
    __shared__ float As[16][136];   // stride 136 = 8 mod 32
    __shared__ float Bs[16][136];
    const int t = threadIdx.x;
    const int lane = t & 31, warp = t >> 5;
    const int row0 = blockIdx.y * 128;
    const int col0 = blockIdx.x * 128;
    const int wm = (warp >> 1) * 32;
    const int wn = (warp & 1) * 64;
    const int m_  = t >> 1;
    const int kb_ = (t & 1) * 8;
    const int gm = row0 + m_;
    const float* arow = x + (size_t)((gm & (SEQ-1))*BSZ + (gm >> 10)) * DIM;
    const int bkr = t >> 4, bc = (t & 15)*8;
    const float* brow = W0 + (size_t)bkr*DIM + col0 + bc;

    DECLC(0,0); DECLC(0,1); DECLC(0,2); DECLC(0,3);
    DECLC(0,4); DECLC(0,5); DECLC(0,6); DECLC(0,7);
    DECLC(1,0); DECLC(1,1); DECLC(1,2); DECLC(1,3);
    DECLC(1,4); DECLC(1,5); DECLC(1,6); DECLC(1,7);

    float4 pa0 = *(const float4*)(arow + kb_);
    float4 pa1 = *(const float4*)(arow + kb_ + 4);
    float4 pb0 = *(const float4*)(brow);
    float4 pb1 = *(const float4*)(brow + 4);

    for(int k0=0; k0<DIM; k0+=16){
        As[kb_+0][m_]=rnaf(pa0.x); As[kb_+1][m_]=rnaf(pa0.y);
        As[kb_+2][m_]=rnaf(pa0.z); As[kb_+3][m_]=rnaf(pa0.w);
        As[kb_+4][m_]=rnaf(pa1.x); As[kb_+5][m_]=rnaf(pa1.y);
        As[kb_+6][m_]=rnaf(pa1.z); As[kb_+7][m_]=rnaf(pa1.w);
        Bs[bkr][bc+0]=rnaf(pb0.x); Bs[bkr][bc+1]=rnaf(pb0.y);
        Bs[bkr][bc+2]=rnaf(pb0.z); Bs[bkr][bc+3]=rnaf(pb0.w);
        Bs[bkr][bc+4]=rnaf(pb1.x); Bs[bkr][bc+5]=rnaf(pb1.y);
        Bs[bkr][bc+6]=rnaf(pb1.z); Bs[bkr][bc+7]=rnaf(pb1.w);
        __syncthreads();
        if(k0 + 16 < DIM){
            pa0 = *(const float4*)(arow + k0 + 16 + kb_);
            pa1 = *(const float4*)(arow + k0 + 16 + kb_ + 4);
            pb0 = *(const float4*)(brow + (size_t)(k0 + 16)*DIM);
            pb1 = *(const float4*)(brow + (size_t)(k0 + 16)*DIM + 4);
        }
        KSTEP(0)
        KSTEP(8)
        __syncthreads();
    }
#define EPI0(mi,ni) { \
    const int gr_ = row0 + wm + mi*16 + (lane>>2); \
    const int gc_ = col0 + wn + ni*8 + 2*(lane&3); \
    g_h0[(size_t)gr_*DIM + gc_    ] = c##mi##ni##_0; \
    g_h0[(size_t)gr_*DIM + gc_ + 1] = c##mi##ni##_1; \
    g_h0[(size_t)(gr_+8)*DIM + gc_    ] = c##mi##ni##_2; \
    g_h0[(size_t)(gr_+8)*DIM + gc_ + 1] = c##mi##ni##_3; }
    EPI0(0,0) EPI0(0,1) EPI0(0,2) EPI0(0,3)
    EPI0(0,4) EPI0(0,5) EPI0(0,6) EPI0(0,7)
    EPI0(1,0) EPI0(1,1) EPI0(1,2) EPI0(1,3)
    EPI0(1,4) EPI0(1,5) EPI0(1,6) EPI0(1,7)
#undef EPI0
}

// GEMM1: out = elu(g_agg1 @ g_wcat + b1) — operands pre-rounded by producers.
__global__ void k_gemm1mma(const float* __restrict__ b1, float* __restrict__ out){
    __shared__ float As[16][136];
    __shared__ float Bs[16][136];
    const int t = threadIdx.x;
    const int lane = t & 31, warp = t >> 5;
    const int row0 = blockIdx.y * 128;
    const int col0 = blockIdx.x * 128;
    const int wm = (warp >> 1) * 32;
    const int wn = (warp & 1) * 64;
    const int m_  = t >> 1;
    const int kb_ = (t & 1) * 8;
    const int gm = row0 + m_;
    const float* arow = g_agg1 + (size_t)gm * (NH*DIM);
    const int bkr = t >> 4, bc = (t & 15)*8;
    const float* brow = g_wcat + (size_t)bkr*DIM + col0 + bc;

    DECLC(0,0); DECLC(0,1); DECLC(0,2); DECLC(0,3);
    DECLC(0,4); DECLC(0,5); DECLC(0,6); DECLC(0,7);
    DECLC(1,0); DECLC(1,1); DECLC(1,2); DECLC(1,3);
    DECLC(1,4); DECLC(1,5); DECLC(1,6); DECLC(1,7);

    float4 pa0 = *(const float4*)(arow + kb_);
    float4 pa1 = *(const float4*)(arow + kb_ + 4);
    float4 pb0 = *(const float4*)(brow);
    float4 pb1 = *(const float4*)(brow + 4);

    for(int k0=0; k0<NH*DIM; k0+=16){
        As[kb_+0][m_]=pa0.x; As[kb_+1][m_]=pa0.y;
        As[kb_+2][m_]=pa0.z; As[kb_+3][m_]=pa0.w;
        As[kb_+4][m_]=pa1.x; As[kb_+5][m_]=pa1.y;
        As[kb_+6][m_]=pa1.z; As[kb_+7][m_]=pa1.w;
        *(float4*)&Bs[bkr][bc]   = pb0;
        *(float4*)&Bs[bkr][bc+4] = pb1;
        __syncthreads();
        if(k0 + 16 < NH*DIM){
            pa0 = *(const float4*)(arow + k0 + 16 + kb_);
            pa1 = *(const float4*)(arow + k0 + 16 + kb_ + 4);
            pb0 = *(const float4*)(brow + (size_t)(k0 + 16)*DIM);
            pb1 = *(const float4*)(brow + (size_t)(k0 + 16)*DIM + 4);
        }
        KSTEP(0)
        KSTEP(8)
        __syncthreads();
    }
#define EPI1(mi,ni) { \
    const int gr_ = row0 + wm + mi*16 + (lane>>2); \
    const int gc_ = col0 + wn + ni*8 + 2*(lane&3); \
    const float bx_ = b1[gc_], by_ = b1[gc_+1]; \
    out[(size_t)gr_*DIM + gc_    ] = eluf(c##mi##ni##_0 + bx_); \
    out[(size_t)gr_*DIM + gc_ + 1] = eluf(c##mi##ni##_1 + by_); \
    out[(size_t)(gr_+8)*DIM + gc_    ] = eluf(c##mi##ni##_2 + bx_); \
    out[(size_t)(gr_+8)*DIM + gc_ + 1] = eluf(c##mi##ni##_3 + by_); }
    EPI1(0,0) EPI1(0,1) EPI1(0,2) EPI1(0,3)
    EPI1(0,4) EPI1(0,5) EPI1(0,6) EPI1(0,7)
    EPI1(1,0) EPI1(1,1) EPI1(1,2) EPI1(1,3)
    EPI1(1,4) EPI1(1,5) EPI1(1,6) EPI1(1,7)
#undef EPI1
}

// ---------------- alpha0: per-node per-head dot with att vectors ----------
__global__ void k_alpha0(const float* __restrict__ as0, const float* __restrict__ ad0){
    int n = blockIdx.x;
    int h = threadIdx.x >> 5, lane = threadIdx.x & 31;
    const float* hp = g_h0 + (size_t)n*DIM + h*64;
    float s=0.f, d=0.f;
    #pragma unroll
    for(int k=lane;k<64;k+=32){ float v=hp[k]; s += v*as0[h*64+k]; d += v*ad0[h*64+k]; }
    s = warpSum(s); d = warpSum(d);
    if(lane==0){ g_asrc0[n*NH+h]=s; g_adst0[n*NH+h]=d; }
}

// ---------------- aggregate0: softmax + weighted sum + bias + elu ---------
__global__ void k_agg0(const float* __restrict__ b0){
    __shared__ int cols_s[128];
    int d = blockIdx.x;
    int t = threadIdx.x;
    int h = t >> 5, lane = t & 31;
    int start = g_rowptr[d], deg = g_rowptr[d+1]-start;
    int ncache = deg < 128 ? deg : 128;
    for(int i=t;i<ncache;i+=256) cols_s[i] = g_col[start+i];
    __syncthreads();
    float adst = g_adst0[d*NH+h];
    float m = -1e30f;
    for(int i=lane;i<deg;i+=32){
        int s = (i<128) ? cols_s[i] : g_col[start+i];
        m = fmaxf(m, lrelu(g_asrc0[s*NH+h]+adst));
    }
    m = warpMax(m);
    float z = 0.f;
    for(int i=lane;i<deg;i+=32){
        int s = (i<128) ? cols_s[i] : g_col[start+i];
        z += __expf(lrelu(g_asrc0[s*NH+h]+adst)-m);
    }
    z = warpSum(z);
    float invz = 1.f/(z + 1e-16f);
    float acc0=0.f, acc1=0.f;
    for(int i=0;i<deg;i++){
        int s = (i<128) ? cols_s[i] : g_col[start+i];
        float w = __expf(lrelu(g_asrc0[s*NH+h]+adst)-m)*invz;
        const float* hp = g_h0 + (size_t)s*DIM + h*64;
        acc0 += w*hp[lane];
        acc1 += w*hp[lane+32];
    }
    int c = h*64 + lane;
    g_h0act[(size_t)d*DIM + c]      = eluf(acc0 + b0[c]);
    g_h0act[(size_t)d*DIM + c + 32] = eluf(acc1 + b0[c+32]);
}

// ---------------- weff1: wsrc[h,k] = sum_c W1[k, h*512+c]*att_src1[h,c] ---
__global__ void k_weff1(const float* __restrict__ W1, const float* __restrict__ as1,
                        const float* __restrict__ ad1){
    int w = blockIdx.x*8 + (threadIdx.x >> 5);
    int lane = threadIdx.x & 31;
    int h = w >> 9, k = w & 511;
    const float* wr = W1 + (size_t)k*(NH*DIM) + h*DIM;
    float s=0.f, d=0.f;
    for(int c=lane;c<DIM;c+=32){ float v=wr[c]; s += v*as1[h*DIM+c]; d += v*ad1[h*DIM+c]; }
    s = warpSum(s); d = warpSum(d);
    if(lane==0){ g_wsrc1[h*DIM+k]=s; g_wdst1[h*DIM+k]=d; }
}

// ---------------- alpha1 -------------------------------------------------
__global__ void k_alpha1(){
    int n = blockIdx.x;
    int h = threadIdx.x >> 5, lane = threadIdx.x & 31;
    const float* hp = g_h0act + (size_t)n*DIM;
    float s=0.f, d=0.f;
    for(int k=lane;k<DIM;k+=32){ float v=hp[k]; s += v*g_wsrc1[h*DIM+k]; d += v*g_wdst1[h*DIM+k]; }
    s = warpSum(s); d = warpSum(d);
    if(lane==0){ g_asrc1[n*NH+h]=s; g_adst1[n*NH+h]=d; }
}

// ---------------- aggregate1: agg[d, h*512+k] = sum_e w[e,h]*h0act[src,k] -
// output tf32-rounded (feeds the mma GEMM)
__global__ void k_agg1(){
    __shared__ float v[512];
    __shared__ float ws[8];
    __shared__ float sm[8];
    __shared__ float sinvz[8];
    __shared__ int cols_s[128];
    int d = blockIdx.x;
    int t = threadIdx.x;
    int warp = t >> 5, lane = t & 31;
    int start = g_rowptr[d], deg = g_rowptr[d+1]-start;
    int ncache = deg < 128 ? deg : 128;
    for(int i=t;i<ncache;i+=256) cols_s[i] = g_col[start+i];
    __syncthreads();
    {
        int h = warp;
        float adst = g_adst1[d*NH+h];
        float m = -1e30f;
        for(int i=lane;i<deg;i+=32){
            int s = (i<128) ? cols_s[i] : g_col[start+i];
            m = fmaxf(m, lrelu(g_asrc1[s*NH+h]+adst));
        }
        m = warpMax(m);
        float z = 0.f;
        for(int i=lane;i<deg;i+=32){
            int s = (i<128) ? cols_s[i] : g_col[start+i];
            z += __expf(lrelu(g_asrc1[s*NH+h]+adst)-m);
        }
        z = warpSum(z);
        if(lane==0){ sm[h]=m; sinvz[h]=1.f/(z+1e-16f); }
    }
    __syncthreads();
    float acc[8][2];
    #pragma unroll
    for(int h=0;h<8;h++){ acc[h][0]=0.f; acc[h][1]=0.f; }
    float adst_l = (t < 8) ? g_adst1[d*NH+t] : 0.f;
    for(int i=0;i<deg;i++){
        int s = (i<128) ? cols_s[i] : g_col[start+i];
        v[t]     = g_h0act[(size_t)s*DIM + t];
        v[t+256] = g_h0act[(size_t)s*DIM + t + 256];
        if(t < 8) ws[t] = __expf(lrelu(g_asrc1[s*NH+t]+adst_l)-sm[t])*sinvz[t];
        __syncthreads();
        float a0 = v[t], a1 = v[t+256];
        float w[8];
        #pragma unroll
        for(int h=0;h<8;h++) w[h] = ws[h];
        #pragma unroll
        for(int h=0;h<8;h++){ acc[h][0] += w[h]*a0; acc[h][1] += w[h]*a1; }
        __syncthreads();
    }
    float* outp = g_agg1 + (size_t)d*(NH*DIM);
    #pragma unroll
    for(int h=0;h<8;h++){
        outp[h*DIM + t]       = rnaf(acc[h][0]);
        outp[h*DIM + t + 256] = rnaf(acc[h][1]);
    }
}

// ---------------- wcat: Wcat[h*512+k, c] = rnaf(W1[k, h*512+c]/8) --------
__global__ void k_wcat(const float* __restrict__ W1){
    int i = blockIdx.x*blockDim.x + threadIdx.x;   // < 4096*512
    int c  = i & 511;
    int kk = i >> 9;          // h*512 + k
    int h = kk >> 9, k = kk & 511;
    g_wcat[i] = rnaf(W1[(size_t)k*(NH*DIM) + h*DIM + c] * 0.125f);
}

// ---------------- launch ----------------
extern "C" void kernel_launch(void* const* d_in, const int* in_sizes, int n_in,
                              void* d_out, int out_size){
    const float* x   = (const float*)d_in[0];
    const int*   edge= (const int*)  d_in[1];
    const float* W0  = (const float*)d_in[2];
    const float* as0 = (const float*)d_in[3];
    const float* ad0 = (const float*)d_in[4];
    const float* b0  = (const float*)d_in[5];
    const float* W1  = (const float*)d_in[6];
    const float* as1 = (const float*)d_in[7];
    const float* ad1 = (const float*)d_in[8];
    const float* b1  = (const float*)d_in[9];
    float* out = (float*)d_out;

    k_zero<<<(NN+255)/256, 256>>>();
    k_count<<<(ETOT+255)/256, 256>>>(edge);
    k_scan<<<1, 1024>>>();
    k_scatter<<<(ETOT+255)/256, 256>>>(edge);

    // layer 0: tf32 mma GEMM (128x128 tiles) + aggregate
    k_gemm0mma<<<dim3(DIM/128, NN/128), 256>>>(x, W0);
    k_alpha0<<<NN, 256>>>(as0, ad0);
    k_agg0<<<NN, 256>>>(b0);

    // layer 1: alpha via precomposed weights, aggregate, then one big GEMM
    k_weff1<<<512, 256>>>(W1, as1, ad1);
    k_alpha1<<<NN, 256>>>();
    k_agg1<<<NN, 256>>>();
    k_wcat<<<(NH*DIM*DIM)/1024, 1024>>>(W1);
    k_gemm1mma<<<dim3(DIM/128, NN/128), 256>>>(b1, out);
}

// round 16
// speedup vs baseline: 1.9400x; 1.2036x over previous

#include <cuda_runtime.h>
#include <cstdint>

#define SEQ 1024
#define BSZ 16
#define DIM 512
#define NH 8
#define NN (SEQ*BSZ)          // 16384 nodes
#define E0 (NN*32)            // 524288 edges
#define ETOT (E0+NN)          // + self loops

// ---------------- scratch (device globals; accessed ONLY by symbol inside
// kernels — never passed as launch arguments from host code) ----------------
__device__ float g_h0[(size_t)NN*DIM];        // nodes @ W0 (pre-aggregation)
__device__ float g_h0act[(size_t)NN*DIM];     // layer0 output (elu)
__device__ float g_asrc0[NN*NH], g_adst0[NN*NH];
__device__ float g_asrc1[NN*NH], g_adst1[NN*NH];
__device__ float g_wsrc1[NH*DIM], g_wdst1[NH*DIM];
__device__ float g_agg1[(size_t)NN*NH*DIM];   // per-head aggregated inputs (tf32-rounded)
__device__ float g_wcat[(size_t)NH*DIM*DIM];  // tf32-rounded permuted W1 * 1/8
__device__ int g_cnt[NN], g_fill[NN], g_rowptr[NN+1], g_col[ETOT];

// ---------------- helpers ----------------
__device__ __forceinline__ float lrelu(float v){ return v > 0.f ? v : 0.2f*v; }
__device__ __forceinline__ float eluf(float v){ return v > 0.f ? v : expm1f(v); }
__device__ __forceinline__ float warpMax(float v){
    #pragma unroll
    for(int o=16;o;o>>=1) v = fmaxf(v, __shfl_xor_sync(0xffffffffu, v, o));
    return v;
}
__device__ __forceinline__ float warpSum(float v){
    #pragma unroll
    for(int o=16;o;o>>=1) v += __shfl_xor_sync(0xffffffffu, v, o);
    return v;
}
// tf32 round-to-nearest in pure C (no asm)
__device__ __forceinline__ float rnaf(float x){
    uint32_t u = __float_as_uint(x);
    u = (u + 0x1000u) & 0xFFFFE000u;
    return __uint_as_float(u);
}
#define MMA_TF32(C0,C1,C2,C3,A0,A1,A2,A3,B0,B1)                               \
    asm volatile(                                                             \
        "mma.sync.aligned.m16n8k8.row.col.f32.tf32.tf32.f32 "                 \
        "{%0,%1,%2,%3}, {%4,%5,%6,%7}, {%8,%9}, {%0,%1,%2,%3};\n"             \
        : "+f"(C0),"+f"(C1),"+f"(C2),"+f"(C3)                                 \
        : "r"(A0),"r"(A1),"r"(A2),"r"(A3), "r"(B0),"r"(B1))
__device__ __forceinline__ void cpa16(uint32_t s, const float* g){
    asm volatile("cp.async.cg.shared.global [%0], [%1], 16;\n" :: "r"(s), "l"(g));
}
__device__ __forceinline__ void cpa_commit(){ asm volatile("cp.async.commit_group;\n"); }
__device__ __forceinline__ void cpa_wait0(){ asm volatile("cp.async.wait_group 0;\n"); }

// ---------------- CSR build ----------------
__global__ void k_zero(){
    int i = blockIdx.x*blockDim.x + threadIdx.x;
    if(i < NN){ g_cnt[i]=0; g_fill[i]=0; }
}
__global__ void k_count(const int* __restrict__ edge){
    int e = blockIdx.x*blockDim.x + threadIdx.x;
    if(e >= ETOT) return;
    int d = (e < E0) ? edge[E0+e] : (e-E0);
    atomicAdd(&g_cnt[d], 1);
}
__global__ void k_scan(){
    __shared__ int sums[1024];
    int t = threadIdx.x;
    int base = t*16;
    int loc[16];
    int s = 0;
    #pragma unroll
    for(int i=0;i<16;i++){ loc[i] = s; s += g_cnt[base+i]; }
    sums[t] = s;
    __syncthreads();
    for(int off=1; off<1024; off<<=1){
        int v = 0;
        if(t >= off) v = sums[t-off];
        __syncthreads();
        if(t >= off) sums[t] += v;
        __syncthreads();
    }
    int pre = (t==0) ? 0 : sums[t-1];
    #pragma unroll
    for(int i=0;i<16;i++) g_rowptr[base+i] = pre + loc[i];
    if(t == 1023) g_rowptr[NN] = sums[1023];
}
__global__ void k_scatter(const int* __restrict__ edge){
    int e = blockIdx.x*blockDim.x + threadIdx.x;
    if(e >= ETOT) return;
    int s, d;
    if(e < E0){ s = edge[e]; d = edge[E0+e]; }
    else { s = e-E0; d = s; }
    int pos = g_rowptr[d] + atomicAdd(&g_fill[d], 1);
    g_col[pos] = s;
}

// =====================================================================
// GEMM0 (round-15 form): tf32 mma, 128x128 tile, LDG/STS staging with
// rnaf rounding; register-prefetch double buffering.
// =====================================================================
#define DECLC(mi,ni) float c##mi##ni##_0=0.f, c##mi##ni##_1=0.f, \
                           c##mi##ni##_2=0.f, c##mi##ni##_3=0.f
#define NSTEP(k8,ni) { \
    const int n_ = wn + ni*8 + (lane>>2); \
    const uint32_t b0_ = __float_as_uint(Bs[(k8)+(lane&3)    ][n_]); \
    const uint32_t b1_ = __float_as_uint(Bs[(k8)+(lane&3) + 4][n_]); \
    MMA_TF32(c0##ni##_0,c0##ni##_1,c0##ni##_2,c0##ni##_3, a00,a01,a02,a03, b0_,b1_); \
    MMA_TF32(c1##ni##_0,c1##ni##_1,c1##ni##_2,c1##ni##_3, a10,a11,a12,a13, b0_,b1_); }
#define KSTEP(k8) { \
    const int r_  = wm + (lane>>2); \
    const int kk_ = (k8) + (lane&3); \
    const uint32_t a00 = __float_as_uint(As[kk_  ][r_   ]); \
    const uint32_t a01 = __float_as_uint(As[kk_  ][r_+ 8]); \
    const uint32_t a02 = __float_as_uint(As[kk_+4][r_   ]); \
    const uint32_t a03 = __float_as_uint(As[kk_+4][r_+ 8]); \
    const uint32_t a10 = __float_as_uint(As[kk_  ][r_+16]); \
    const uint32_t a11 = __float_as_uint(As[kk_  ][r_+24]); \
    const uint32_t a12 = __float_as_uint(As[kk_+4][r_+16]); \
    const uint32_t a13 = __float_as_uint(As[kk_+4][r_+24]); \
    NSTEP(k8,0) NSTEP(k8,1) NSTEP(k8,2) NSTEP(k8,3) \
    NSTEP(k8,4) NSTEP(k8,5) NSTEP(k8,6) NSTEP(k8,7) }

__global__ void k_gemm0mma(const float* __restrict__ x, const float* __restrict__ W0){
    __shared__ float As[16][136];
    __shared__ float Bs[16][136];
    const int t = threadIdx.x;
    const int lane = t & 31, warp = t >> 5;
    const int row0 = blockIdx.y * 128;
    const int col0 = blockIdx.x * 128;
    const int wm = (warp >> 1) * 32;
    const int wn = (warp & 1) * 64;
    const int m_  = t >> 1;
    const int kb_ = (t & 1) * 8;
    const int gm = row0 + m_;
    const float* arow = x + (size_t)((gm & (SEQ-1))*BSZ + (gm >> 10)) * DIM;
    const int bkr = t >> 4, bc = (t & 15)*8;
    const float* brow = W0 + (size_t)bkr*DIM + col0 + bc;

    DECLC(0,0); DECLC(0,1); DECLC(0,2); DECLC(0,3);
    DECLC(0,4); DECLC(0,5); DECLC(0,6); DECLC(0,7);
    DECLC(1,0); DECLC(1,1); DECLC(1,2); DECLC(1,3);
    DECLC(1,4); DECLC(1,5); DECLC(1,6); DECLC(1,7);

    float4 pa0 = *(const float4*)(arow + kb_);
    float4 pa1 = *(const float4*)(arow + kb_ + 4);
    float4 pb0 = *(const float4*)(brow);
    float4 pb1 = *(const float4*)(brow + 4);

    for(int k0=0; k0<DIM; k0+=16){
        As[kb_+0][m_]=rnaf(pa0.x); As[kb_+1][m_]=rnaf(pa0.y);
        As[kb_+2][m_]=rnaf(pa0.z); As[kb_+3][m_]=rnaf(pa0.w);
        As[kb_+4][m_]=rnaf(pa1.x); As[kb_+5][m_]=rnaf(pa1.y);
        As[kb_+6][m_]=rnaf(pa1.z); As[kb_+7][m_]=rnaf(pa1.w);
        Bs[bkr][bc+0]=rnaf(pb0.x); Bs[bkr][bc+1]=rnaf(pb0.y);
        Bs[bkr][bc+2]=rnaf(pb0.z); Bs[bkr][bc+3]=rnaf(pb0.w);
        Bs[bkr][bc+4]=rnaf(pb1.x); Bs[bkr][bc+5]=rnaf(pb1.y);
        Bs[bkr][bc+6]=rnaf(pb1.z); Bs[bkr][bc+7]=rnaf(pb1.w);
        __syncthreads();
        if(k0 + 16 < DIM){
            pa0 = *(const float4*)(arow + k0 + 16 + kb_);
            pa1 = *(const float4*)(arow + k0 + 16 + kb_ + 4);
            pb0 = *(const float4*)(brow + (size_t)(k0 + 16)*DIM);
            pb1 = *(const float4*)(brow + (size_t)(k0 + 16)*DIM + 4);
        }
        KSTEP(0)
        KSTEP(8)
        __syncthreads();
    }
#define EPI0(mi,ni) { \
    const int gr_ = row0 + wm + mi*16 + (lane>>2); \
    const int gc_ = col0 + wn + ni*8 + 2*(lane&3); \
    g_h0[(size_t)gr_*DIM + gc_    ] = c##mi##ni##_0; \
    g_h0[(size_t)gr_*DIM + gc_ + 1] = c##mi##ni##_1; \
    g_h0[(size_t)(gr_+8)*DIM + gc_    ] = c##mi##ni##_2; \
    g_h0[(size_t)(gr_+8)*DIM + gc_ + 1] = c##mi##ni##_3; }
    EPI0(0,0) EPI0(0,1) EPI0(0,2) EPI0(0,3)
    EPI0(0,4) EPI0(0,5) EPI0(0,6) EPI0(0,7)
    EPI0(1,0) EPI0(1,1) EPI0(1,2) EPI0(1,3)
    EPI0(1,4) EPI0(1,5) EPI0(1,6) EPI0(1,7)
#undef EPI0
}

// =====================================================================
// GEMM1: cp.async double-buffered tf32 mma, 128x128 tile, BK=16.
//   As[2][128][20] (m-major, stride 20: banks 20q+s distinct)
//   Bs[2][16][136] (k-major, stride 136: banks 8s+q distinct)
//   Operands pre-rounded to tf32 by producers (k_agg1 / k_wcat).
// =====================================================================
#define NSTEP1(k8,ni) { \
    const int n_ = wn + ni*8 + (lane>>2); \
    const uint32_t b0_ = __float_as_uint(Bb[(k8)+(lane&3)    ][n_]); \
    const uint32_t b1_ = __float_as_uint(Bb[(k8)+(lane&3) + 4][n_]); \
    MMA_TF32(c0##ni##_0,c0##ni##_1,c0##ni##_2,c0##ni##_3, a00,a01,a02,a03, b0_,b1_); \
    MMA_TF32(c1##ni##_0,c1##ni##_1,c1##ni##_2,c1##ni##_3, a10,a11,a12,a13, b0_,b1_); }
#define KSTEP1(k8) { \
    const int r_  = wm + (lane>>2); \
    const int kk_ = (k8) + (lane&3); \
    const uint32_t a00 = __float_as_uint(Ab[r_   ][kk_  ]); \
    const uint32_t a01 = __float_as_uint(Ab[r_+ 8][kk_  ]); \
    const uint32_t a02 = __float_as_uint(Ab[r_   ][kk_+4]); \
    const uint32_t a03 = __float_as_uint(Ab[r_+ 8][kk_+4]); \
    const uint32_t a10 = __float_as_uint(Ab[r_+16][kk_  ]); \
    const uint32_t a11 = __float_as_uint(Ab[r_+24][kk_  ]); \
    const uint32_t a12 = __float_as_uint(Ab[r_+16][kk_+4]); \
    const uint32_t a13 = __float_as_uint(Ab[r_+24][kk_+4]); \
    NSTEP1(k8,0) NSTEP1(k8,1) NSTEP1(k8,2) NSTEP1(k8,3) \
    NSTEP1(k8,4) NSTEP1(k8,5) NSTEP1(k8,6) NSTEP1(k8,7) }

__global__ void k_gemm1mma(const float* __restrict__ b1, float* __restrict__ out){
    __shared__ float As[2][128][20];
    __shared__ float Bs[2][16][136];
    const int t = threadIdx.x;
    const int lane = t & 31, warp = t >> 5;
    const int row0 = blockIdx.y * 128;
    const int col0 = blockIdx.x * 128;
    const int wm = (warp >> 1) * 32;
    const int wn = (warp & 1) * 64;

    // copy plans: A 128x16 floats = 512 float4, 2/thread (rows ar, ar+64)
    const int ar = t >> 2, ac4 = t & 3;
    const float* aG = g_agg1 + (size_t)(row0 + ar)*(NH*DIM) + ac4*4;
    // B 16x128 floats = 512 float4, 2/thread (k-rows bkr, bkr+8)
    const int bkr = t >> 5, bc4 = t & 31;
    const float* bG = g_wcat + (size_t)bkr*DIM + col0 + bc4*4;

    const uint32_t asB = (uint32_t)__cvta_generic_to_shared(&As[0][0][0]);
    const uint32_t bsB = (uint32_t)__cvta_generic_to_shared(&Bs[0][0][0]);
    const uint32_t aOff = (uint32_t)(ar*20 + ac4*4)*4;
    const uint32_t bOff = (uint32_t)(bkr*136 + bc4*4)*4;
    const uint32_t aBuf = 128*20*4, bBuf = 16*136*4;
    const uint32_t aJ = 64*20*4, bJ = 8*136*4;

    DECLC(0,0); DECLC(0,1); DECLC(0,2); DECLC(0,3);
    DECLC(0,4); DECLC(0,5); DECLC(0,6); DECLC(0,7);
    DECLC(1,0); DECLC(1,1); DECLC(1,2); DECLC(1,3);
    DECLC(1,4); DECLC(1,5); DECLC(1,6); DECLC(1,7);

    // preload tile 0 -> buf 0
    cpa16(asB + aOff,      aG);
    cpa16(asB + aOff + aJ, aG + (size_t)64*(NH*DIM));
    cpa16(bsB + bOff,      bG);
    cpa16(bsB + bOff + bJ, bG + (size_t)8*DIM);
    cpa_commit();

    const int T = (NH*DIM)/16;
    for(int kt=0; kt<T; kt++){
        cpa_wait0();
        __syncthreads();
        if(kt+1 < T){
            const int nb = (kt+1)&1;
            const float* aN = aG + (kt+1)*16;
            const float* bN = bG + (size_t)(kt+1)*16*DIM;
            cpa16(asB + nb*aBuf + aOff,      aN);
            cpa16(asB + nb*aBuf + aOff + aJ, aN + (size_t)64*(NH*DIM));
            cpa16(bsB + nb*bBuf + bOff,      bN);
            cpa16(bsB + nb*bBuf + bOff + bJ, bN + (size_t)8*DIM);
            cpa_commit();
        }
        const int cb = kt&1;
        const float (* __restrict__ Ab)[20]  = As[cb];
        const float (* __restrict__ Bb)[136] = Bs[cb];
        KSTEP1(0)
        KSTEP1(8)
        __syncthreads();
    }
#define EPI1(mi,ni) { \
    const int gr_ = row0 + wm + mi*16 + (lane>>2); \
    const int gc_ = col0 + wn + ni*8 + 2*(lane&3); \
    const float bx_ = b1[gc_], by_ = b1[gc_+1]; \
    out[(size_t)gr_*DIM + gc_    ] = eluf(c##mi##ni##_0 + bx_); \
    out[(size_t)gr_*DIM + gc_ + 1] = eluf(c##mi##ni##_1 + by_); \
    out[(size_t)(gr_+8)*DIM + gc_    ] = eluf(c##mi##ni##_2 + bx_); \
    out[(size_t)(gr_+8)*DIM + gc_ + 1] = eluf(c##mi##ni##_3 + by_); }
    EPI1(0,0) EPI1(0,1) EPI1(0,2) EPI1(0,3)
    EPI1(0,4) EPI1(0,5) EPI1(0,6) EPI1(0,7)
    EPI1(1,0) EPI1(1,1) EPI1(1,2) EPI1(1,3)
    EPI1(1,4) EPI1(1,5) EPI1(1,6) EPI1(1,7)
#undef EPI1
}

// ---------------- alpha0 ----------
__global__ void k_alpha0(const float* __restrict__ as0, const float* __restrict__ ad0){
    int n = blockIdx.x;
    int h = threadIdx.x >> 5, lane = threadIdx.x & 31;
    const float* hp = g_h0 + (size_t)n*DIM + h*64;
    float s=0.f, d=0.f;
    #pragma unroll
    for(int k=lane;k<64;k+=32){ float v=hp[k]; s += v*as0[h*64+k]; d += v*ad0[h*64+k]; }
    s = warpSum(s); d = warpSum(d);
    if(lane==0){ g_asrc0[n*NH+h]=s; g_adst0[n*NH+h]=d; }
}

// ---------------- aggregate0 ----------
__global__ void k_agg0(const float* __restrict__ b0){
    __shared__ int cols_s[128];
    int d = blockIdx.x;
    int t = threadIdx.x;
    int h = t >> 5, lane = t & 31;
    int start = g_rowptr[d], deg = g_rowptr[d+1]-start;
    int ncache = deg < 128 ? deg : 128;
    for(int i=t;i<ncache;i+=256) cols_s[i] = g_col[start+i];
    __syncthreads();
    float adst = g_adst0[d*NH+h];
    float m = -1e30f;
    for(int i=lane;i<deg;i+=32){
        int s = (i<128) ? cols_s[i] : g_col[start+i];
        m = fmaxf(m, lrelu(g_asrc0[s*NH+h]+adst));
    }
    m = warpMax(m);
    float z = 0.f;
    for(int i=lane;i<deg;i+=32){
        int s = (i<128) ? cols_s[i] : g_col[start+i];
        z += __expf(lrelu(g_asrc0[s*NH+h]+adst)-m);
    }
    z = warpSum(z);
    float invz = 1.f/(z + 1e-16f);
    float acc0=0.f, acc1=0.f;
    for(int i=0;i<deg;i++){
        int s = (i<128) ? cols_s[i] : g_col[start+i];
        float w = __expf(lrelu(g_asrc0[s*NH+h]+adst)-m)*invz;
        const float* hp = g_h0 + (size_t)s*DIM + h*64;
        acc0 += w*hp[lane];
        acc1 += w*hp[lane+32];
    }
    int c = h*64 + lane;
    g_h0act[(size_t)d*DIM + c]      = eluf(acc0 + b0[c]);
    g_h0act[(size_t)d*DIM + c + 32] = eluf(acc1 + b0[c+32]);
}

// ---------------- weff1 ----------
__global__ void k_weff1(const float* __restrict__ W1, const float* __restrict__ as1,
                        const float* __restrict__ ad1){
    int w = blockIdx.x*8 + (threadIdx.x >> 5);
    int lane = threadIdx.x & 31;
    int h = w >> 9, k = w & 511;
    const float* wr = W1 + (size_t)k*(NH*DIM) + h*DIM;
    float s=0.f, d=0.f;
    for(int c=lane;c<DIM;c+=32){ float v=wr[c]; s += v*as1[h*DIM+c]; d += v*ad1[h*DIM+c]; }
    s = warpSum(s); d = warpSum(d);
    if(lane==0){ g_wsrc1[h*DIM+k]=s; g_wdst1[h*DIM+k]=d; }
}

// ---------------- alpha1 ----------
__global__ void k_alpha1(){
    int n = blockIdx.x;
    int h = threadIdx.x >> 5, lane = threadIdx.x & 31;
    const float* hp = g_h0act + (size_t)n*DIM;
    float s=0.f, d=0.f;
    for(int k=lane;k<DIM;k+=32){ float v=hp[k]; s += v*g_wsrc1[h*DIM+k]; d += v*g_wdst1[h*DIM+k]; }
    s = warpSum(s); d = warpSum(d);
    if(lane==0){ g_asrc1[n*NH+h]=s; g_adst1[n*NH+h]=d; }
}

// ---------------- aggregate1: chunked 4 edges per sync round -------------
__global__ void k_agg1(){
    __shared__ float v4[4][512];
    __shared__ float ws4[4][8];
    __shared__ float sm[8], sinvz[8], adst_s[8];
    __shared__ int cols_s[128];
    int d = blockIdx.x;
    int t = threadIdx.x;
    int warp = t >> 5, lane = t & 31;
    int start = g_rowptr[d], deg = g_rowptr[d+1]-start;
    int ncache = deg < 128 ? deg : 128;
    for(int i=t;i<ncache;i+=256) cols_s[i] = g_col[start+i];
    __syncthreads();
    {
        int h = warp;
        float adst = g_adst1[d*NH+h];
        float m = -1e30f;
        for(int i=lane;i<deg;i+=32){
            int s = (i<128) ? cols_s[i] : g_col[start+i];
            m = fmaxf(m, lrelu(g_asrc1[s*NH+h]+adst));
        }
        m = warpMax(m);
        float z = 0.f;
        for(int i=lane;i<deg;i+=32){
            int s = (i<128) ? cols_s[i] : g_col[start+i];
            z += __expf(lrelu(g_asrc1[s*NH+h]+adst)-m);
        }
        z = warpSum(z);
        if(lane==0){ sm[h]=m; sinvz[h]=1.f/(z+1e-16f); adst_s[h]=adst; }
    }
    __syncthreads();
    float acc[8][2];
    #pragma unroll
    for(int h=0;h<8;h++){ acc[h][0]=0.f; acc[h][1]=0.f; }
    for(int i0=0;i0<deg;i0+=4){
        // load up to 4 source rows + compute their weights
        #pragma unroll
        for(int c=0;c<4;c++){
            int i = i0 + c;
            if(i < deg){
                int s = (i<128) ? cols_s[i] : g_col[start+i];
                v4[c][t]     = g_h0act[(size_t)s*DIM + t];
                v4[c][t+256] = g_h0act[(size_t)s*DIM + t + 256];
            }
        }
        if(t < 32){
            int c = t >> 3, h = t & 7;
            int i = i0 + c;
            float w = 0.f;
            if(i < deg){
                int s = (i<128) ? cols_s[i] : g_col[start+i];
                w = __expf(lrelu(g_asrc1[s*NH+h]+adst_s[h])-sm[h])*sinvz[h];
            }
            ws4[c][h] = w;
        }
        __syncthreads();
        #pragma unroll
        for(int c=0;c<4;c++){
            float a0 = v4[c][t], a1 = v4[c][t+256];
            #pragma unroll
            for(int h=0;h<8;h++){
                float w = ws4[c][h];
                acc[h][0] += w*a0;
                acc[h][1] += w*a1;
            }
        }
        __syncthreads();
    }
    float* outp = g_agg1 + (size_t)d*(NH*DIM);
    #pragma unroll
    for(int h=0;h<8;h++){
        outp[h*DIM + t]       = rnaf(acc[h][0]);
        outp[h*DIM + t + 256] = rnaf(acc[h][1]);
    }
}

// ---------------- wcat ----------
__global__ void k_wcat(const float* __restrict__ W1){
    int i = blockIdx.x*blockDim.x + threadIdx.x;   // < 4096*512
    int c  = i & 511;
    int kk = i >> 9;          // h*512 + k
    int h = kk >> 9, k = kk & 511;
    g_wcat[i] = rnaf(W1[(size_t)k*(NH*DIM) + h*DIM + c] * 0.125f);
}

// ---------------- launch ----------------
extern "C" void kernel_launch(void* const* d_in, const int* in_sizes, int n_in,
                              void* d_out, int out_size){
    const float* x   = (const float*)d_in[0];
    const int*   edge= (const int*)  d_in[1];
    const float* W0  = (const float*)d_in[2];
    const float* as0 = (const float*)d_in[3];
    const float* ad0 = (const float*)d_in[4];
    const float* b0  = (const float*)d_in[5];
    const float* W1  = (const float*)d_in[6];
    const float* as1 = (const float*)d_in[7];
    const float* ad1 = (const float*)d_in[8];
    const float* b1  = (const float*)d_in[9];
    float* out = (float*)d_out;

    k_zero<<<(NN+255)/256, 256>>>();
    k_count<<<(ETOT+255)/256, 256>>>(edge);
    k_scan<<<1, 1024>>>();
    k_scatter<<<(ETOT+255)/256, 256>>>(edge);

    // layer 0
    k_gemm0mma<<<dim3(DIM/128, NN/128), 256>>>(x, W0);
    k_alpha0<<<NN, 256>>>(as0, ad0);
    k_agg0<<<NN, 256>>>(b0);

    // layer 1
    k_weff1<<<512, 256>>>(W1, as1, ad1);
    k_alpha1<<<NN, 256>>>();
    k_agg1<<<NN, 256>>>();
    k_wcat<<<(NH*DIM*DIM)/1024, 1024>>>(W1);
    k_gemm1mma<<<dim3(DIM/128, NN/128), 256>>>(b1, out);
}